// round 1
// baseline (speedup 1.0000x reference)
#include <cuda_runtime.h>
#include <cuda_bf16.h>
#include <math.h>

// ---------------------------------------------------------------------------
// EnhancedTransformerBlock  B=8 S=1024 H=1024 nh=16 hd=64  (fp32 baseline)
// ---------------------------------------------------------------------------

#define Bsz   8
#define Ssz   1024
#define Hsz   1024
#define NH    16
#define HD    64
#define Mrows (Bsz*Ssz)          // 8192
#define HF    (4*Hsz)            // 4096
#define HG    (Hsz/2)            // 512

// ------------------------- scratch (device globals) ------------------------
__device__ float g_Q  [(size_t)Mrows*Hsz];
__device__ float g_K  [(size_t)Mrows*Hsz];
__device__ float g_V  [(size_t)Mrows*Hsz];
__device__ float g_S  [(size_t)Bsz*NH*Ssz*Ssz];   // 512 MB scores/attn
__device__ float g_ctx[(size_t)Mrows*Hsz];
__device__ float g_xr [(size_t)Mrows*Hsz];        // x + attn_out
__device__ float g_x1 [(size_t)Mrows*Hsz];        // post adaLN1
__device__ float g_h  [(size_t)Mrows*HF];         // gelu(ffn1)
__device__ float g_f  [(size_t)Mrows*Hsz];        // ffn_out
__device__ float g_g1 [(size_t)Mrows*HG];         // relu(gate1)
__device__ float g_g  [(size_t)Mrows*Hsz];        // sigmoid(gate2)

// ------------------------------- GEMM --------------------------------------
// C = act(alpha * A@B (+bias)) (+resid), optional batched offsets via z.
// ACT: 0 none, 1 gelu(exact), 2 relu, 3 sigmoid.
template<int ACT, bool TRANSB>
__global__ __launch_bounds__(256)
void gemm_kernel(const float* __restrict__ A, int lda, long long oA1, long long oA2,
                 const float* __restrict__ B, int ldb, long long oB1, long long oB2,
                 float*       __restrict__ C, int ldc, long long oC1, long long oC2,
                 const float* __restrict__ bias,
                 const float* __restrict__ resid,
                 int M, int N, int K, int zdiv, float alpha)
{
    const int z  = blockIdx.z;
    const int zb = z / zdiv, zr = z % zdiv;
    A += zb*oA1 + zr*oA2;
    B += zb*oB1 + zr*oB2;
    const long long coff = zb*oC1 + zr*oC2;
    C += coff;
    if (resid) resid += coff;

    __shared__ float As[8][128];
    __shared__ float Bs[8][128];

    const int tid = threadIdx.x;
    const int tr  = tid >> 4;          // 0..15
    const int tc  = tid & 15;          // 0..15

    float acc[8][8];
    #pragma unroll
    for (int i = 0; i < 8; i++)
        #pragma unroll
        for (int j = 0; j < 8; j++) acc[i][j] = 0.f;

    const int rowA = tid >> 1;                 // 0..127
    const int colA = (tid & 1) * 4;            // 0 or 4
    const int rowB = tid >> 5;                 // 0..7   (no trans)
    const int colB = (tid & 31) * 4;           // 0..124
    const int n0base = blockIdx.x * 128;
    const int m0base = blockIdx.y * 128;

    const float* Ab = A + (long long)(m0base + rowA) * lda;

    for (int kt = 0; kt < K; kt += 8) {
        // ---- load A tile (128 x 8), store transposed ----
        {
            float4 a4 = *(const float4*)(Ab + kt + colA);
            As[colA+0][rowA] = a4.x;
            As[colA+1][rowA] = a4.y;
            As[colA+2][rowA] = a4.z;
            As[colA+3][rowA] = a4.w;
        }
        // ---- load B tile ----
        if (!TRANSB) {
            const int n0 = n0base + colB;
            const float* bp = B + (long long)(kt + rowB) * ldb + n0;
            if (n0 + 3 < N) {
                float4 b4 = *(const float4*)bp;
                Bs[rowB][colB+0] = b4.x;
                Bs[rowB][colB+1] = b4.y;
                Bs[rowB][colB+2] = b4.z;
                Bs[rowB][colB+3] = b4.w;
            } else {
                #pragma unroll
                for (int j = 0; j < 4; j++)
                    Bs[rowB][colB+j] = (n0 + j < N) ? bp[j] : 0.f;
            }
        } else {
            const int n = n0base + rowA;       // reuse rowA/colA mapping
            if (n < N) {
                float4 b4 = *(const float4*)(B + (long long)n * ldb + kt + colA);
                Bs[colA+0][rowA] = b4.x;
                Bs[colA+1][rowA] = b4.y;
                Bs[colA+2][rowA] = b4.z;
                Bs[colA+3][rowA] = b4.w;
            } else {
                #pragma unroll
                for (int j = 0; j < 4; j++) Bs[colA+j][rowA] = 0.f;
            }
        }
        __syncthreads();

        #pragma unroll
        for (int kk = 0; kk < 8; kk++) {
            float ra[8], rb[8];
            #pragma unroll
            for (int i = 0; i < 8; i++) ra[i] = As[kk][tr*8 + i];
            #pragma unroll
            for (int j = 0; j < 8; j++) rb[j] = Bs[kk][tc*8 + j];
            #pragma unroll
            for (int i = 0; i < 8; i++)
                #pragma unroll
                for (int j = 0; j < 8; j++) acc[i][j] = fmaf(ra[i], rb[j], acc[i][j]);
        }
        __syncthreads();
    }

    // ---- epilogue ----
    #pragma unroll
    for (int i = 0; i < 8; i++) {
        const int row = m0base + tr*8 + i;
        #pragma unroll
        for (int j = 0; j < 8; j++) {
            const int col = n0base + tc*8 + j;
            if (col < N) {
                float v = acc[i][j] * alpha;
                if (bias) v += bias[col];
                if (ACT == 1) v = 0.5f * v * (1.0f + erff(v * 0.70710678118654752f));
                else if (ACT == 2) v = fmaxf(v, 0.f);
                else if (ACT == 3) v = 1.f / (1.f + expf(-v));
                if (resid) v += resid[(long long)row * ldc + col];
                C[(long long)row * ldc + col] = v;
            }
        }
    }
}

// ----------------------------- softmax rows --------------------------------
// one block (128 threads) per row of 1024
__global__ __launch_bounds__(128)
void softmax_kernel(float* __restrict__ S)
{
    float* row = S + (long long)blockIdx.x * 1024;
    const int t = threadIdx.x;
    float4 v0 = *(float4*)(row + t*4);
    float4 v1 = *(float4*)(row + 512 + t*4);

    __shared__ float sm[4];
    const int lane = t & 31, w = t >> 5;

    float m = fmaxf(fmaxf(fmaxf(v0.x, v0.y), fmaxf(v0.z, v0.w)),
                    fmaxf(fmaxf(v1.x, v1.y), fmaxf(v1.z, v1.w)));
    #pragma unroll
    for (int o = 16; o; o >>= 1) m = fmaxf(m, __shfl_xor_sync(0xffffffffu, m, o));
    if (lane == 0) sm[w] = m;
    __syncthreads();
    m = fmaxf(fmaxf(sm[0], sm[1]), fmaxf(sm[2], sm[3]));
    __syncthreads();

    v0.x = expf(v0.x - m); v0.y = expf(v0.y - m); v0.z = expf(v0.z - m); v0.w = expf(v0.w - m);
    v1.x = expf(v1.x - m); v1.y = expf(v1.y - m); v1.z = expf(v1.z - m); v1.w = expf(v1.w - m);

    float s = v0.x + v0.y + v0.z + v0.w + v1.x + v1.y + v1.z + v1.w;
    #pragma unroll
    for (int o = 16; o; o >>= 1) s += __shfl_xor_sync(0xffffffffu, s, o);
    if (lane == 0) sm[w] = s;
    __syncthreads();
    s = sm[0] + sm[1] + sm[2] + sm[3];
    const float inv = 1.f / s;

    v0.x *= inv; v0.y *= inv; v0.z *= inv; v0.w *= inv;
    v1.x *= inv; v1.y *= inv; v1.z *= inv; v1.w *= inv;
    *(float4*)(row + t*4)       = v0;
    *(float4*)(row + 512 + t*4) = v1;
}

// -------------------------- block reduce (256 thr) --------------------------
__device__ __forceinline__ float blk_sum256(float v)
{
    __shared__ float sm[8];
    const int lane = threadIdx.x & 31, w = threadIdx.x >> 5;
    #pragma unroll
    for (int o = 16; o; o >>= 1) v += __shfl_xor_sync(0xffffffffu, v, o);
    if (lane == 0) sm[w] = v;
    __syncthreads();
    if (w == 0) {
        float r = (lane < 8) ? sm[lane] : 0.f;
        #pragma unroll
        for (int o = 4; o; o >>= 1) r += __shfl_xor_sync(0xffffffffu, r, o);
        if (lane == 0) sm[0] = r;
    }
    __syncthreads();
    float r = sm[0];
    __syncthreads();
    return r;
}

// ------------------------------- adaLN --------------------------------------
// out = LN(in)*(1+sigmoid(vol*vsw+vsb))*gamma + beta ; 256 thr, 4 elems/thr
__global__ __launch_bounds__(256)
void ada_ln_kernel(const float* __restrict__ in, const float* __restrict__ vol,
                   const float* __restrict__ w, const float* __restrict__ b,
                   const float* __restrict__ gamma, const float* __restrict__ beta,
                   const float* __restrict__ vsw, const float* __restrict__ vsb,
                   float* __restrict__ out)
{
    const long long row = blockIdx.x;
    const int t = threadIdx.x;
    float4 v = *(const float4*)(in + row*1024 + t*4);

    float mu = blk_sum256(v.x + v.y + v.z + v.w) * (1.f/1024.f);
    float dx = v.x - mu, dy = v.y - mu, dz = v.z - mu, dw = v.w - mu;
    float var = blk_sum256(dx*dx + dy*dy + dz*dz + dw*dw) * (1.f/1024.f);
    float inv = rsqrtf(var + 1e-5f);

    float vs = 1.f / (1.f + expf(-(vol[row] * (*vsw) + (*vsb))));
    float k1 = (1.f + vs) * (*gamma);
    float k0 = *beta;

    float4 w4 = *(const float4*)(w + t*4);
    float4 b4 = *(const float4*)(b + t*4);
    float4 o;
    o.x = (dx*inv*w4.x + b4.x) * k1 + k0;
    o.y = (dy*inv*w4.y + b4.y) * k1 + k0;
    o.z = (dz*inv*w4.z + b4.z) * k1 + k0;
    o.w = (dw*inv*w4.w + b4.w) * k1 + k0;
    *(float4*)(out + row*1024 + t*4) = o;
}

// -------- combine (x1*(2-g) + ffn*g) then adaLN2 -> out ----------------------
__global__ __launch_bounds__(256)
void combine_ada_ln_kernel(const float* __restrict__ x1, const float* __restrict__ f,
                           const float* __restrict__ g,  const float* __restrict__ vol,
                           const float* __restrict__ w,  const float* __restrict__ b,
                           const float* __restrict__ gamma, const float* __restrict__ beta,
                           const float* __restrict__ vsw, const float* __restrict__ vsb,
                           float* __restrict__ out)
{
    const long long row = blockIdx.x;
    const int t = threadIdx.x;
    float4 a = *(const float4*)(x1 + row*1024 + t*4);
    float4 ff = *(const float4*)(f  + row*1024 + t*4);
    float4 gg = *(const float4*)(g  + row*1024 + t*4);

    float4 v;
    v.x = a.x*(2.f-gg.x) + ff.x*gg.x;
    v.y = a.y*(2.f-gg.y) + ff.y*gg.y;
    v.z = a.z*(2.f-gg.z) + ff.z*gg.z;
    v.w = a.w*(2.f-gg.w) + ff.w*gg.w;

    float mu = blk_sum256(v.x + v.y + v.z + v.w) * (1.f/1024.f);
    float dx = v.x - mu, dy = v.y - mu, dz = v.z - mu, dw = v.w - mu;
    float var = blk_sum256(dx*dx + dy*dy + dz*dz + dw*dw) * (1.f/1024.f);
    float inv = rsqrtf(var + 1e-5f);

    float vs = 1.f / (1.f + expf(-(vol[row] * (*vsw) + (*vsb))));
    float k1 = (1.f + vs) * (*gamma);
    float k0 = *beta;

    float4 w4 = *(const float4*)(w + t*4);
    float4 b4 = *(const float4*)(b + t*4);
    float4 o;
    o.x = (dx*inv*w4.x + b4.x) * k1 + k0;
    o.y = (dy*inv*w4.y + b4.y) * k1 + k0;
    o.z = (dz*inv*w4.z + b4.z) * k1 + k0;
    o.w = (dw*inv*w4.w + b4.w) * k1 + k0;
    *(float4*)(out + row*1024 + t*4) = o;
}

// ------------------------------ launcher ------------------------------------
extern "C" void kernel_launch(void* const* d_in, const int* in_sizes, int n_in,
                              void* d_out, int out_size)
{
    const float* x      = (const float*)d_in[0];
    const float* vol    = (const float*)d_in[1];
    const float* Wq     = (const float*)d_in[2];
    const float* bq     = (const float*)d_in[3];
    const float* Wk     = (const float*)d_in[4];
    const float* bk     = (const float*)d_in[5];
    const float* Wv     = (const float*)d_in[6];
    const float* bv     = (const float*)d_in[7];
    const float* Wo     = (const float*)d_in[8];
    const float* bo     = (const float*)d_in[9];
    const float* ln1w   = (const float*)d_in[10];
    const float* ln1b   = (const float*)d_in[11];
    const float* gamma1 = (const float*)d_in[12];
    const float* beta1  = (const float*)d_in[13];
    const float* vs1w   = (const float*)d_in[14];
    const float* vs1b   = (const float*)d_in[15];
    const float* fw1    = (const float*)d_in[16];
    const float* fb1    = (const float*)d_in[17];
    const float* fw2    = (const float*)d_in[18];
    const float* fb2    = (const float*)d_in[19];
    const float* gw1    = (const float*)d_in[20];
    const float* gb1    = (const float*)d_in[21];
    const float* gw2    = (const float*)d_in[22];
    const float* gb2    = (const float*)d_in[23];
    const float* ln2w   = (const float*)d_in[24];
    const float* ln2b   = (const float*)d_in[25];
    const float* gamma2 = (const float*)d_in[26];
    const float* beta2  = (const float*)d_in[27];
    const float* vs2w   = (const float*)d_in[28];
    const float* vs2b   = (const float*)d_in[29];
    float* out = (float*)d_out;

    float *Q, *Kb, *Vb, *Sb, *ctx, *xr, *x1, *h, *f, *g1, *g;
    cudaGetSymbolAddress((void**)&Q,   g_Q);
    cudaGetSymbolAddress((void**)&Kb,  g_K);
    cudaGetSymbolAddress((void**)&Vb,  g_V);
    cudaGetSymbolAddress((void**)&Sb,  g_S);
    cudaGetSymbolAddress((void**)&ctx, g_ctx);
    cudaGetSymbolAddress((void**)&xr,  g_xr);
    cudaGetSymbolAddress((void**)&x1,  g_x1);
    cudaGetSymbolAddress((void**)&h,   g_h);
    cudaGetSymbolAddress((void**)&f,   g_f);
    cudaGetSymbolAddress((void**)&g1,  g_g1);
    cudaGetSymbolAddress((void**)&g,   g_g);

    const long long SH = (long long)Ssz * Hsz;      // 1048576
    const long long SS = (long long)Ssz * Ssz;      // 1048576

    // Q, K, V projections
    gemm_kernel<0,false><<<dim3(8,64,1),256>>>(x,Hsz,0,0, Wq,Hsz,0,0, Q,Hsz,0,0, bq,nullptr, Mrows,Hsz,Hsz, 1, 1.f);
    gemm_kernel<0,false><<<dim3(8,64,1),256>>>(x,Hsz,0,0, Wk,Hsz,0,0, Kb,Hsz,0,0, bk,nullptr, Mrows,Hsz,Hsz, 1, 1.f);
    gemm_kernel<0,false><<<dim3(8,64,1),256>>>(x,Hsz,0,0, Wv,Hsz,0,0, Vb,Hsz,0,0, bv,nullptr, Mrows,Hsz,Hsz, 1, 1.f);

    // scores[b,h] = Q[b,:,h,:] @ K[b,:,h,:]^T / 8
    gemm_kernel<0,true><<<dim3(8,8,Bsz*NH),256>>>(Q,Hsz,SH,HD, Kb,Hsz,SH,HD,
                                                  Sb,Ssz,(long long)NH*SS,SS,
                                                  nullptr,nullptr, Ssz,Ssz,HD, NH, 0.125f);
    // softmax over last dim
    softmax_kernel<<<Bsz*NH*Ssz,128>>>(Sb);

    // ctx[b,:,h,:] = attn[b,h] @ V[b,:,h,:]
    gemm_kernel<0,false><<<dim3(1,8,Bsz*NH),256>>>(Sb,Ssz,(long long)NH*SS,SS, Vb,Hsz,SH,HD,
                                                   ctx,Hsz,SH,HD,
                                                   nullptr,nullptr, Ssz,HD,Ssz, NH, 1.f);

    // attn_out + residual: xr = ctx @ Wo + bo + x
    gemm_kernel<0,false><<<dim3(8,64,1),256>>>(ctx,Hsz,0,0, Wo,Hsz,0,0, xr,Hsz,0,0, bo,x, Mrows,Hsz,Hsz, 1, 1.f);

    // adaLN1
    ada_ln_kernel<<<Mrows,256>>>(xr, vol, ln1w, ln1b, gamma1, beta1, vs1w, vs1b, x1);

    // FFN: h = gelu(x1@W1+b1); f = h@W2+b2
    gemm_kernel<1,false><<<dim3(32,64,1),256>>>(x1,Hsz,0,0, fw1,HF,0,0, h,HF,0,0, fb1,nullptr, Mrows,HF,Hsz, 1, 1.f);
    gemm_kernel<0,false><<<dim3(8,64,1),256>>>(h,HF,0,0, fw2,Hsz,0,0, f,Hsz,0,0, fb2,nullptr, Mrows,Hsz,HF, 1, 1.f);

    // gate: g1 = relu(x1@gw1+gb1); g = sigmoid(g1@gw2+gb2)
    gemm_kernel<2,false><<<dim3(4,64,1),256>>>(x1,Hsz,0,0, gw1,HG,0,0, g1,HG,0,0, gb1,nullptr, Mrows,HG,Hsz, 1, 1.f);
    gemm_kernel<3,false><<<dim3(8,64,1),256>>>(g1,HG,0,0, gw2,Hsz,0,0, g,Hsz,0,0, gb2,nullptr, Mrows,Hsz,HG, 1, 1.f);

    // combine + adaLN2 -> out
    combine_ada_ln_kernel<<<Mrows,256>>>(x1, f, g, vol, ln2w, ln2b, gamma2, beta2, vs2w, vs2b, out);
}

// round 3
// speedup vs baseline: 1.6187x; 1.6187x over previous
#include <cuda_runtime.h>
#include <cuda_bf16.h>
#include <math.h>
#include <stdint.h>

// ---------------------------------------------------------------------------
// EnhancedTransformerBlock  B=8 S=1024 H=1024 nh=16 hd=64
// mma.sync m16n8k8 TF32 GEMMs (fp32 I/O, fp32 accum) + fused elementwise
// ---------------------------------------------------------------------------

#define Bsz   8
#define Ssz   1024
#define Hsz   1024
#define NH    16
#define HD    64
#define Mrows (Bsz*Ssz)          // 8192
#define HF    (4*Hsz)            // 4096
#define HG    (Hsz/2)            // 512

// ------------------------- scratch (device globals) ------------------------
__device__ float g_Q  [(size_t)Mrows*Hsz];
__device__ float g_K  [(size_t)Mrows*Hsz];
__device__ float g_V  [(size_t)Mrows*Hsz];
__device__ float g_Vt [(size_t)Mrows*Hsz];        // (b,h,d,s) permuted V
__device__ float g_S  [(size_t)Bsz*NH*Ssz*Ssz];   // 512 MB scores/attn
__device__ float g_ctx[(size_t)Mrows*Hsz];
__device__ float g_xr [(size_t)Mrows*Hsz];        // x + attn_out
__device__ float g_x1 [(size_t)Mrows*Hsz];        // post adaLN1
__device__ float g_h  [(size_t)Mrows*HF];         // gelu(ffn1)
__device__ float g_f  [(size_t)Mrows*Hsz];        // ffn_out
__device__ float g_g1 [(size_t)Mrows*HG];         // relu(gate1)
__device__ float g_g  [(size_t)Mrows*Hsz];        // sigmoid(gate2)
// transposed weights (stored [N][K] K-major)
__device__ float g_WqT [(size_t)Hsz*Hsz];
__device__ float g_WkT [(size_t)Hsz*Hsz];
__device__ float g_WvT [(size_t)Hsz*Hsz];
__device__ float g_WoT [(size_t)Hsz*Hsz];
__device__ float g_fw1T[(size_t)Hsz*HF];
__device__ float g_fw2T[(size_t)HF*Hsz];
__device__ float g_gw1T[(size_t)Hsz*HG];
__device__ float g_gw2T[(size_t)HG*Hsz];

// ------------------------------ helpers ------------------------------------
__device__ __forceinline__ uint32_t f2tf32(float x) {
    uint32_t u;
    asm("cvt.rna.tf32.f32 %0, %1;" : "=r"(u) : "f"(x));
    return u;
}
__device__ __forceinline__ void mma_tf32(float* c, const uint32_t* a, const uint32_t* b) {
    asm volatile(
        "mma.sync.aligned.m16n8k8.row.col.f32.tf32.tf32.f32 "
        "{%0,%1,%2,%3}, {%4,%5,%6,%7}, {%8,%9}, {%0,%1,%2,%3};"
        : "+f"(c[0]), "+f"(c[1]), "+f"(c[2]), "+f"(c[3])
        : "r"(a[0]), "r"(a[1]), "r"(a[2]), "r"(a[3]), "r"(b[0]), "r"(b[1]));
}
// word index inside a [32 k][W m] tile; swizzle keeps both staging stores and
// fragment loads bank-conflict-free (verified: banks = m ^ (k&3)<<3 ^ (k>>2)<<2)
__device__ __forceinline__ int swz(int k, int m, int W) {
    return k * W + (m ^ ((k & 3) << 3) ^ (((k >> 2) & 7) << 2));
}

// ----------------------------- TF32 GEMM -----------------------------------
// C[m,n] = act(alpha * sum_k A[m,k]*B[n,k] + bias[n]) (+resid)
// A: [M,K] K-major, B: [N,K] K-major. M%128==0, N%NT==0, K%32==0.
// act: 0 none, 1 gelu, 2 relu, 3 sigmoid
template<int NT>
__global__ __launch_bounds__(256)
void mma_gemm(const float* __restrict__ A, int lda, long long oA1, long long oA2,
              const float* __restrict__ B, int ldb, long long oB1, long long oB2,
              float*       __restrict__ C, int ldc, long long oC1, long long oC2,
              const float* __restrict__ bias, const float* __restrict__ resid,
              int K, int zdiv, float alpha, int act)
{
    constexpr int BI = NT / 32;      // B float4 loads per thread
    constexpr int NI = NT / 32;      // n sub-tiles per warp (each 8 wide)
    constexpr int WN = NT / 4;       // warp n-tile width
    constexpr int AW = 128, BW = NT; // tile widths (m / n)

    extern __shared__ uint32_t smem[];
    uint32_t* As[2] = { smem,             smem + 32 * 128 };
    uint32_t* Bs[2] = { smem + 64 * 128,  smem + 64 * 128 + 32 * NT };

    const int tid = threadIdx.x, wid = tid >> 5, lane = tid & 31;
    const int gid = lane >> 2, tig = lane & 3;
    const int warpm = wid & 1, warpn = wid >> 1;

    const int z  = blockIdx.z;
    const int zb = z / zdiv, zr = z - zb * zdiv;
    A += zb * oA1 + zr * oA2;
    B += zb * oB1 + zr * oB2;
    const long long coff = zb * oC1 + zr * oC2;
    C += coff;
    if (resid) resid += coff;

    const int m0 = blockIdx.y * 128;
    const int n0 = blockIdx.x * NT;
    const int ar = tid >> 3, aq = tid & 7;   // staging row/k-quad

    float c[4][NI][4];
    #pragma unroll
    for (int mi = 0; mi < 4; mi++)
        #pragma unroll
        for (int ni = 0; ni < NI; ni++)
            #pragma unroll
            for (int e = 0; e < 4; e++) c[mi][ni][e] = 0.f;

    float4 fa[4], fb[BI];

    // ---- prologue: load + store chunk 0 ----
    #pragma unroll
    for (int i = 0; i < 4; i++)
        fa[i] = *(const float4*)(A + (long long)(m0 + ar + i * 32) * lda + aq * 4);
    #pragma unroll
    for (int i = 0; i < BI; i++)
        fb[i] = *(const float4*)(B + (long long)(n0 + ar + i * 32) * ldb + aq * 4);
    #pragma unroll
    for (int i = 0; i < 4; i++) {
        int r = ar + i * 32, k0 = aq * 4;
        As[0][swz(k0+0, r, AW)] = f2tf32(fa[i].x);
        As[0][swz(k0+1, r, AW)] = f2tf32(fa[i].y);
        As[0][swz(k0+2, r, AW)] = f2tf32(fa[i].z);
        As[0][swz(k0+3, r, AW)] = f2tf32(fa[i].w);
    }
    #pragma unroll
    for (int i = 0; i < BI; i++) {
        int r = ar + i * 32, k0 = aq * 4;
        Bs[0][swz(k0+0, r, BW)] = f2tf32(fb[i].x);
        Bs[0][swz(k0+1, r, BW)] = f2tf32(fb[i].y);
        Bs[0][swz(k0+2, r, BW)] = f2tf32(fb[i].z);
        Bs[0][swz(k0+3, r, BW)] = f2tf32(fb[i].w);
    }
    __syncthreads();

    const int nch = K >> 5;
    for (int ch = 0; ch < nch; ch++) {
        const int buf = ch & 1;
        // prefetch next chunk to regs
        if (ch + 1 < nch) {
            const int kt = (ch + 1) * 32;
            #pragma unroll
            for (int i = 0; i < 4; i++)
                fa[i] = *(const float4*)(A + (long long)(m0 + ar + i * 32) * lda + kt + aq * 4);
            #pragma unroll
            for (int i = 0; i < BI; i++)
                fb[i] = *(const float4*)(B + (long long)(n0 + ar + i * 32) * ldb + kt + aq * 4);
        }
        // compute current chunk
        const uint32_t* Ab = As[buf];
        const uint32_t* Bb = Bs[buf];
        #pragma unroll
        for (int ks = 0; ks < 4; ks++) {
            uint32_t a[4][4], b[NI][2];
            const int k0 = ks * 8 + tig;
            #pragma unroll
            for (int mi = 0; mi < 4; mi++) {
                const int row = warpm * 64 + mi * 16 + gid;
                a[mi][0] = Ab[swz(k0,     row,     AW)];
                a[mi][1] = Ab[swz(k0,     row + 8, AW)];
                a[mi][2] = Ab[swz(k0 + 4, row,     AW)];
                a[mi][3] = Ab[swz(k0 + 4, row + 8, AW)];
            }
            #pragma unroll
            for (int ni = 0; ni < NI; ni++) {
                const int col = warpn * WN + ni * 8 + gid;
                b[ni][0] = Bb[swz(k0,     col, BW)];
                b[ni][1] = Bb[swz(k0 + 4, col, BW)];
            }
            #pragma unroll
            for (int mi = 0; mi < 4; mi++)
                #pragma unroll
                for (int ni = 0; ni < NI; ni++)
                    mma_tf32(c[mi][ni], a[mi], b[ni]);
        }
        // store next chunk
        if (ch + 1 < nch) {
            uint32_t* An = As[buf ^ 1];
            uint32_t* Bn = Bs[buf ^ 1];
            #pragma unroll
            for (int i = 0; i < 4; i++) {
                int r = ar + i * 32, k0 = aq * 4;
                An[swz(k0+0, r, AW)] = f2tf32(fa[i].x);
                An[swz(k0+1, r, AW)] = f2tf32(fa[i].y);
                An[swz(k0+2, r, AW)] = f2tf32(fa[i].z);
                An[swz(k0+3, r, AW)] = f2tf32(fa[i].w);
            }
            #pragma unroll
            for (int i = 0; i < BI; i++) {
                int r = ar + i * 32, k0 = aq * 4;
                Bn[swz(k0+0, r, BW)] = f2tf32(fb[i].x);
                Bn[swz(k0+1, r, BW)] = f2tf32(fb[i].y);
                Bn[swz(k0+2, r, BW)] = f2tf32(fb[i].z);
                Bn[swz(k0+3, r, BW)] = f2tf32(fb[i].w);
            }
        }
        __syncthreads();
    }

    // ------------------------------ epilogue --------------------------------
    #pragma unroll
    for (int mi = 0; mi < 4; mi++) {
        #pragma unroll
        for (int ni = 0; ni < NI; ni++) {
            const int col = n0 + warpn * WN + ni * 8 + 2 * tig;
            float bx = 0.f, by = 0.f;
            if (bias) { bx = bias[col]; by = bias[col + 1]; }
            #pragma unroll
            for (int h = 0; h < 2; h++) {
                const int row = m0 + warpm * 64 + mi * 16 + gid + h * 8;
                float v0 = c[mi][ni][2*h + 0] * alpha + bx;
                float v1 = c[mi][ni][2*h + 1] * alpha + by;
                if (act == 1) {
                    v0 = 0.5f * v0 * (1.0f + erff(v0 * 0.70710678118654752f));
                    v1 = 0.5f * v1 * (1.0f + erff(v1 * 0.70710678118654752f));
                } else if (act == 2) {
                    v0 = fmaxf(v0, 0.f); v1 = fmaxf(v1, 0.f);
                } else if (act == 3) {
                    v0 = 1.f / (1.f + expf(-v0)); v1 = 1.f / (1.f + expf(-v1));
                }
                const long long g = (long long)row * ldc + col;
                if (resid) {
                    float2 q = *(const float2*)(resid + g);
                    v0 += q.x; v1 += q.y;
                }
                float2 o; o.x = v0; o.y = v1;
                *(float2*)(C + g) = o;
            }
        }
    }
}

// ---------------------------- batched transpose -----------------------------
__global__ __launch_bounds__(256)
void transpose_kernel(const float* __restrict__ in, int ldi, long long oI1, long long oI2,
                      float* __restrict__ out, int ldo, long long oO1, long long oO2,
                      int zdiv)
{
    const int z = blockIdx.z, zb = z / zdiv, zr = z - zb * zdiv;
    in  += zb * oI1 + zr * oI2;
    out += zb * oO1 + zr * oO2;
    __shared__ float t[32][33];
    const int r0 = blockIdx.y * 32, c0 = blockIdx.x * 32;
    const int tx = threadIdx.x & 31, ty = threadIdx.x >> 5;
    #pragma unroll
    for (int i = 0; i < 32; i += 8)
        t[ty + i][tx] = in[(long long)(r0 + ty + i) * ldi + c0 + tx];
    __syncthreads();
    #pragma unroll
    for (int i = 0; i < 32; i += 8)
        out[(long long)(c0 + ty + i) * ldo + r0 + tx] = t[tx][ty + i];
}

// ----------------------------- softmax rows --------------------------------
__global__ __launch_bounds__(128)
void softmax_kernel(float* __restrict__ S)
{
    float* row = S + (long long)blockIdx.x * 1024;
    const int t = threadIdx.x;
    float4 v0 = *(float4*)(row + t * 4);
    float4 v1 = *(float4*)(row + 512 + t * 4);

    __shared__ float sm[4];
    const int lane = t & 31, w = t >> 5;

    float m = fmaxf(fmaxf(fmaxf(v0.x, v0.y), fmaxf(v0.z, v0.w)),
                    fmaxf(fmaxf(v1.x, v1.y), fmaxf(v1.z, v1.w)));
    #pragma unroll
    for (int o = 16; o; o >>= 1) m = fmaxf(m, __shfl_xor_sync(0xffffffffu, m, o));
    if (lane == 0) sm[w] = m;
    __syncthreads();
    m = fmaxf(fmaxf(sm[0], sm[1]), fmaxf(sm[2], sm[3]));
    __syncthreads();

    v0.x = expf(v0.x - m); v0.y = expf(v0.y - m); v0.z = expf(v0.z - m); v0.w = expf(v0.w - m);
    v1.x = expf(v1.x - m); v1.y = expf(v1.y - m); v1.z = expf(v1.z - m); v1.w = expf(v1.w - m);

    float s = v0.x + v0.y + v0.z + v0.w + v1.x + v1.y + v1.z + v1.w;
    #pragma unroll
    for (int o = 16; o; o >>= 1) s += __shfl_xor_sync(0xffffffffu, s, o);
    if (lane == 0) sm[w] = s;
    __syncthreads();
    s = sm[0] + sm[1] + sm[2] + sm[3];
    const float inv = 1.f / s;

    v0.x *= inv; v0.y *= inv; v0.z *= inv; v0.w *= inv;
    v1.x *= inv; v1.y *= inv; v1.z *= inv; v1.w *= inv;
    *(float4*)(row + t * 4)       = v0;
    *(float4*)(row + 512 + t * 4) = v1;
}

// -------------------------- block reduce (256 thr) --------------------------
__device__ __forceinline__ float blk_sum256(float v)
{
    __shared__ float sm[8];
    const int lane = threadIdx.x & 31, w = threadIdx.x >> 5;
    #pragma unroll
    for (int o = 16; o; o >>= 1) v += __shfl_xor_sync(0xffffffffu, v, o);
    if (lane == 0) sm[w] = v;
    __syncthreads();
    if (w == 0) {
        float r = (lane < 8) ? sm[lane] : 0.f;
        #pragma unroll
        for (int o = 4; o; o >>= 1) r += __shfl_xor_sync(0xffffffffu, r, o);
        if (lane == 0) sm[0] = r;
    }
    __syncthreads();
    float r = sm[0];
    __syncthreads();
    return r;
}

// ------------------------------- adaLN --------------------------------------
__global__ __launch_bounds__(256)
void ada_ln_kernel(const float* __restrict__ in, const float* __restrict__ vol,
                   const float* __restrict__ w, const float* __restrict__ b,
                   const float* __restrict__ gamma, const float* __restrict__ beta,
                   const float* __restrict__ vsw, const float* __restrict__ vsb,
                   float* __restrict__ out)
{
    const long long row = blockIdx.x;
    const int t = threadIdx.x;
    float4 v = *(const float4*)(in + row * 1024 + t * 4);

    float mu = blk_sum256(v.x + v.y + v.z + v.w) * (1.f / 1024.f);
    float dx = v.x - mu, dy = v.y - mu, dz = v.z - mu, dw = v.w - mu;
    float var = blk_sum256(dx * dx + dy * dy + dz * dz + dw * dw) * (1.f / 1024.f);
    float inv = rsqrtf(var + 1e-5f);

    float vs = 1.f / (1.f + expf(-(vol[row] * (*vsw) + (*vsb))));
    float k1 = (1.f + vs) * (*gamma);
    float k0 = *beta;

    float4 w4 = *(const float4*)(w + t * 4);
    float4 b4 = *(const float4*)(b + t * 4);
    float4 o;
    o.x = (dx * inv * w4.x + b4.x) * k1 + k0;
    o.y = (dy * inv * w4.y + b4.y) * k1 + k0;
    o.z = (dz * inv * w4.z + b4.z) * k1 + k0;
    o.w = (dw * inv * w4.w + b4.w) * k1 + k0;
    *(float4*)(out + row * 1024 + t * 4) = o;
}

// -------- combine (x1*(2-g) + ffn*g) then adaLN2 -> out ----------------------
__global__ __launch_bounds__(256)
void combine_ada_ln_kernel(const float* __restrict__ x1, const float* __restrict__ f,
                           const float* __restrict__ g,  const float* __restrict__ vol,
                           const float* __restrict__ w,  const float* __restrict__ b,
                           const float* __restrict__ gamma, const float* __restrict__ beta,
                           const float* __restrict__ vsw, const float* __restrict__ vsb,
                           float* __restrict__ out)
{
    const long long row = blockIdx.x;
    const int t = threadIdx.x;
    float4 a  = *(const float4*)(x1 + row * 1024 + t * 4);
    float4 ff = *(const float4*)(f  + row * 1024 + t * 4);
    float4 gg = *(const float4*)(g  + row * 1024 + t * 4);

    float4 v;
    v.x = a.x * (2.f - gg.x) + ff.x * gg.x;
    v.y = a.y * (2.f - gg.y) + ff.y * gg.y;
    v.z = a.z * (2.f - gg.z) + ff.z * gg.z;
    v.w = a.w * (2.f - gg.w) + ff.w * gg.w;

    float mu = blk_sum256(v.x + v.y + v.z + v.w) * (1.f / 1024.f);
    float dx = v.x - mu, dy = v.y - mu, dz = v.z - mu, dw = v.w - mu;
    float var = blk_sum256(dx * dx + dy * dy + dz * dz + dw * dw) * (1.f / 1024.f);
    float inv = rsqrtf(var + 1e-5f);

    float vs = 1.f / (1.f + expf(-(vol[row] * (*vsw) + (*vsb))));
    float k1 = (1.f + vs) * (*gamma);
    float k0 = *beta;

    float4 w4 = *(const float4*)(w + t * 4);
    float4 b4 = *(const float4*)(b + t * 4);
    float4 o;
    o.x = (dx * inv * w4.x + b4.x) * k1 + k0;
    o.y = (dy * inv * w4.y + b4.y) * k1 + k0;
    o.z = (dz * inv * w4.z + b4.z) * k1 + k0;
    o.w = (dw * inv * w4.w + b4.w) * k1 + k0;
    *(float4*)(out + row * 1024 + t * 4) = o;
}

// ------------------------------ launcher ------------------------------------
#define SMEM_G128 (2 * (32*128 + 32*128) * 4)   // 65536
#define SMEM_G64  (2 * (32*128 + 32*64)  * 4)   // 49152

extern "C" void kernel_launch(void* const* d_in, const int* in_sizes, int n_in,
                              void* d_out, int out_size)
{
    const float* x      = (const float*)d_in[0];
    const float* vol    = (const float*)d_in[1];
    const float* Wq     = (const float*)d_in[2];
    const float* bq     = (const float*)d_in[3];
    const float* Wk     = (const float*)d_in[4];
    const float* bk     = (const float*)d_in[5];
    const float* Wv     = (const float*)d_in[6];
    const float* bv     = (const float*)d_in[7];
    const float* Wo     = (const float*)d_in[8];
    const float* bo     = (const float*)d_in[9];
    const float* ln1w   = (const float*)d_in[10];
    const float* ln1b   = (const float*)d_in[11];
    const float* gamma1 = (const float*)d_in[12];
    const float* beta1  = (const float*)d_in[13];
    const float* vs1w   = (const float*)d_in[14];
    const float* vs1b   = (const float*)d_in[15];
    const float* fw1    = (const float*)d_in[16];
    const float* fb1    = (const float*)d_in[17];
    const float* fw2    = (const float*)d_in[18];
    const float* fb2    = (const float*)d_in[19];
    const float* gw1    = (const float*)d_in[20];
    const float* gb1    = (const float*)d_in[21];
    const float* gw2    = (const float*)d_in[22];
    const float* gb2    = (const float*)d_in[23];
    const float* ln2w   = (const float*)d_in[24];
    const float* ln2b   = (const float*)d_in[25];
    const float* gamma2 = (const float*)d_in[26];
    const float* beta2  = (const float*)d_in[27];
    const float* vs2w   = (const float*)d_in[28];
    const float* vs2b   = (const float*)d_in[29];
    float* out = (float*)d_out;

    float *Q, *Kb, *Vb, *Vt, *Sb, *ctx, *xr, *x1, *h, *f, *g1, *g;
    float *WqT, *WkT, *WvT, *WoT, *fw1T, *fw2T, *gw1T, *gw2T;
    cudaGetSymbolAddress((void**)&Q,    g_Q);
    cudaGetSymbolAddress((void**)&Kb,   g_K);
    cudaGetSymbolAddress((void**)&Vb,   g_V);
    cudaGetSymbolAddress((void**)&Vt,   g_Vt);
    cudaGetSymbolAddress((void**)&Sb,   g_S);
    cudaGetSymbolAddress((void**)&ctx,  g_ctx);
    cudaGetSymbolAddress((void**)&xr,   g_xr);
    cudaGetSymbolAddress((void**)&x1,   g_x1);
    cudaGetSymbolAddress((void**)&h,    g_h);
    cudaGetSymbolAddress((void**)&f,    g_f);
    cudaGetSymbolAddress((void**)&g1,   g_g1);
    cudaGetSymbolAddress((void**)&g,    g_g);
    cudaGetSymbolAddress((void**)&WqT,  g_WqT);
    cudaGetSymbolAddress((void**)&WkT,  g_WkT);
    cudaGetSymbolAddress((void**)&WvT,  g_WvT);
    cudaGetSymbolAddress((void**)&WoT,  g_WoT);
    cudaGetSymbolAddress((void**)&fw1T, g_fw1T);
    cudaGetSymbolAddress((void**)&fw2T, g_fw2T);
    cudaGetSymbolAddress((void**)&gw1T, g_gw1T);
    cudaGetSymbolAddress((void**)&gw2T, g_gw2T);

    cudaFuncSetAttribute(mma_gemm<128>, cudaFuncAttributeMaxDynamicSharedMemorySize, SMEM_G128);
    cudaFuncSetAttribute(mma_gemm<64>,  cudaFuncAttributeMaxDynamicSharedMemorySize, SMEM_G64);

    const long long SH = (long long)Ssz * Hsz;      // 1048576
    const long long SS = (long long)Ssz * Ssz;      // 1048576

    // ---- weight transposes (W[K,N] -> WT[N,K]) ----
    transpose_kernel<<<dim3(Hsz/32, Hsz/32, 1), 256>>>(Wq, Hsz, 0,0, WqT, Hsz, 0,0, 1);
    transpose_kernel<<<dim3(Hsz/32, Hsz/32, 1), 256>>>(Wk, Hsz, 0,0, WkT, Hsz, 0,0, 1);
    transpose_kernel<<<dim3(Hsz/32, Hsz/32, 1), 256>>>(Wv, Hsz, 0,0, WvT, Hsz, 0,0, 1);
    transpose_kernel<<<dim3(Hsz/32, Hsz/32, 1), 256>>>(Wo, Hsz, 0,0, WoT, Hsz, 0,0, 1);
    transpose_kernel<<<dim3(HF/32,  Hsz/32, 1), 256>>>(fw1, HF, 0,0, fw1T, Hsz, 0,0, 1);
    transpose_kernel<<<dim3(Hsz/32, HF/32,  1), 256>>>(fw2, Hsz, 0,0, fw2T, HF, 0,0, 1);
    transpose_kernel<<<dim3(HG/32,  Hsz/32, 1), 256>>>(gw1, HG, 0,0, gw1T, Hsz, 0,0, 1);
    transpose_kernel<<<dim3(Hsz/32, HG/32,  1), 256>>>(gw2, Hsz, 0,0, gw2T, HG, 0,0, 1);

    // ---- QKV projections ----
    mma_gemm<128><<<dim3(8,64,1),256,SMEM_G128>>>(x,Hsz,0,0, WqT,Hsz,0,0, Q,Hsz,0,0, bq,nullptr, Hsz,1, 1.f,0);
    mma_gemm<128><<<dim3(8,64,1),256,SMEM_G128>>>(x,Hsz,0,0, WkT,Hsz,0,0, Kb,Hsz,0,0, bk,nullptr, Hsz,1, 1.f,0);
    mma_gemm<128><<<dim3(8,64,1),256,SMEM_G128>>>(x,Hsz,0,0, WvT,Hsz,0,0, Vb,Hsz,0,0, bv,nullptr, Hsz,1, 1.f,0);

    // ---- scores = Q @ K^T / 8 (batched over b,h) ----
    mma_gemm<128><<<dim3(8,8,Bsz*NH),256,SMEM_G128>>>(Q,Hsz,SH,HD, Kb,Hsz,SH,HD,
                                                      Sb,Ssz,(long long)NH*SS,SS,
                                                      nullptr,nullptr, HD,NH, 0.125f,0);
    // ---- softmax ----
    softmax_kernel<<<Bsz*NH*Ssz,128>>>(Sb);

    // ---- V permute: Vt[b,h,d,s] = V[b,s,h*64+d] ----
    transpose_kernel<<<dim3(2,32,Bsz*NH),256>>>(Vb, Hsz, SH, HD,
                                                Vt, Ssz, (long long)NH*HD*Ssz, (long long)HD*Ssz, NH);

    // ---- ctx = attn @ V ----
    mma_gemm<64><<<dim3(1,8,Bsz*NH),256,SMEM_G64>>>(Sb,Ssz,(long long)NH*SS,SS,
                                                    Vt,Ssz,(long long)NH*HD*Ssz,(long long)HD*Ssz,
                                                    ctx,Hsz,SH,HD,
                                                    nullptr,nullptr, Ssz,NH, 1.f,0);

    // ---- O projection + residual ----
    mma_gemm<128><<<dim3(8,64,1),256,SMEM_G128>>>(ctx,Hsz,0,0, WoT,Hsz,0,0, xr,Hsz,0,0, bo,x, Hsz,1, 1.f,0);

    // ---- adaLN1 ----
    ada_ln_kernel<<<Mrows,256>>>(xr, vol, ln1w, ln1b, gamma1, beta1, vs1w, vs1b, x1);

    // ---- FFN ----
    mma_gemm<128><<<dim3(32,64,1),256,SMEM_G128>>>(x1,Hsz,0,0, fw1T,Hsz,0,0, h,HF,0,0,  fb1,nullptr, Hsz,1, 1.f,1);
    mma_gemm<128><<<dim3(8,64,1), 256,SMEM_G128>>>(h,HF,0,0,  fw2T,HF,0,0,  f,Hsz,0,0,  fb2,nullptr, HF,1,  1.f,0);

    // ---- gate ----
    mma_gemm<128><<<dim3(4,64,1),256,SMEM_G128>>>(x1,Hsz,0,0, gw1T,Hsz,0,0, g1,HG,0,0, gb1,nullptr, Hsz,1, 1.f,2);
    mma_gemm<128><<<dim3(8,64,1),256,SMEM_G128>>>(g1,HG,0,0,  gw2T,HG,0,0,  g,Hsz,0,0, gb2,nullptr, HG,1,  1.f,3);

    // ---- combine + adaLN2 -> out ----
    combine_ada_ln_kernel<<<Mrows,256>>>(x1, f, g, vol, ln2w, ln2b, gamma2, beta2, vs2w, vs2b, out);
}

// round 4
// speedup vs baseline: 2.6657x; 1.6468x over previous
#include <cuda_runtime.h>
#include <cuda_bf16.h>
#include <cuda_fp16.h>
#include <math.h>
#include <stdint.h>

// ---------------------------------------------------------------------------
// EnhancedTransformerBlock  B=8 S=1024 H=1024 nh=16 hd=64
// mma.sync m16n8k16 FP16 GEMMs (fp32 I/O, fp32 accum) + fused elementwise
// ---------------------------------------------------------------------------

#define Bsz   8
#define Ssz   1024
#define Hsz   1024
#define NH    16
#define HD    64
#define Mrows (Bsz*Ssz)          // 8192
#define HF    (4*Hsz)            // 4096
#define HG    (Hsz/2)            // 512

// ------------------------- scratch (device globals) ------------------------
__device__ float g_Q  [(size_t)Mrows*Hsz];
__device__ float g_K  [(size_t)Mrows*Hsz];
__device__ float g_V  [(size_t)Mrows*Hsz];
__device__ float g_Vt [(size_t)Mrows*Hsz];        // (b,h,d,s) permuted V
__device__ float g_S  [(size_t)Bsz*NH*Ssz*Ssz];   // 512 MB scores/attn
__device__ float g_ctx[(size_t)Mrows*Hsz];
__device__ float g_xr [(size_t)Mrows*Hsz];        // x + attn_out
__device__ float g_x1 [(size_t)Mrows*Hsz];        // post adaLN1
__device__ float g_h  [(size_t)Mrows*HF];         // gelu(ffn1)
__device__ float g_f  [(size_t)Mrows*Hsz];        // ffn_out
__device__ float g_g1 [(size_t)Mrows*HG];         // relu(gate1)
__device__ float g_g  [(size_t)Mrows*Hsz];        // sigmoid(gate2)
// transposed weights (stored [N][K] K-major)
__device__ float g_WqT [(size_t)Hsz*Hsz];
__device__ float g_WkT [(size_t)Hsz*Hsz];
__device__ float g_WvT [(size_t)Hsz*Hsz];
__device__ float g_WoT [(size_t)Hsz*Hsz];
__device__ float g_fw1T[(size_t)Hsz*HF];
__device__ float g_fw2T[(size_t)HF*Hsz];
__device__ float g_gw1T[(size_t)Hsz*HG];
__device__ float g_gw2T[(size_t)HG*Hsz];

// ------------------------------ helpers ------------------------------------
__device__ __forceinline__ uint32_t pack_h2(float lo, float hi) {
    __half2 h = __floats2half2_rn(lo, hi);
    return *(uint32_t*)&h;
}
__device__ __forceinline__ void mma_f16(float* c, const uint32_t* a, const uint32_t* b) {
    asm volatile(
        "mma.sync.aligned.m16n8k16.row.col.f32.f16.f16.f32 "
        "{%0,%1,%2,%3}, {%4,%5,%6,%7}, {%8,%9}, {%0,%1,%2,%3};"
        : "+f"(c[0]), "+f"(c[1]), "+f"(c[2]), "+f"(c[3])
        : "r"(a[0]), "r"(a[1]), "r"(a[2]), "r"(a[3]), "r"(b[0]), "r"(b[1]));
}
// word index inside a [16 kp][W m] tile of half2 words; swizzle keeps both
// staging stores and fragment loads 32-bank conflict-free
__device__ __forceinline__ int swz(int kp, int m, int W) {
    return kp * W + (m ^ ((kp & 3) << 3) ^ (((kp >> 2) & 7) << 2));
}

// ----------------------------- FP16 GEMM -----------------------------------
// C[m,n] = act(alpha * sum_k A[m,k]*B[n,k] + bias[n]) (+resid)
// A: [M,K] K-major, B: [N,K] K-major. M%128==0, N%NT==0, K%32==0.
// act: 0 none, 1 gelu, 2 relu, 3 sigmoid
template<int NT>
__global__ __launch_bounds__(256)
void mma_gemm(const float* __restrict__ A, int lda, long long oA1, long long oA2,
              const float* __restrict__ B, int ldb, long long oB1, long long oB2,
              float*       __restrict__ C, int ldc, long long oC1, long long oC2,
              const float* __restrict__ bias, const float* __restrict__ resid,
              int K, int zdiv, float alpha, int act)
{
    constexpr int BI = NT / 32;      // B float4 loads per thread
    constexpr int NI = NT / 32;      // n sub-tiles per warp (each 8 wide)
    constexpr int WN = NT / 4;       // warp n-tile width
    constexpr int AW = 128, BW = NT; // tile widths (m / n)

    extern __shared__ uint32_t smem[];
    uint32_t* As[2] = { smem,             smem + 16 * 128 };
    uint32_t* Bs[2] = { smem + 32 * 128,  smem + 32 * 128 + 16 * NT };

    const int tid = threadIdx.x, wid = tid >> 5, lane = tid & 31;
    const int gid = lane >> 2, tig = lane & 3;
    const int warpm = wid & 1, warpn = wid >> 1;

    const int z  = blockIdx.z;
    const int zb = z / zdiv, zr = z - zb * zdiv;
    A += zb * oA1 + zr * oA2;
    B += zb * oB1 + zr * oB2;
    const long long coff = zb * oC1 + zr * oC2;
    C += coff;
    if (resid) resid += coff;

    const int m0 = blockIdx.y * 128;
    const int n0 = blockIdx.x * NT;
    const int ar = tid >> 3, aq = tid & 7;   // staging row / k-quad (4 floats)

    float c[4][NI][4];
    #pragma unroll
    for (int mi = 0; mi < 4; mi++)
        #pragma unroll
        for (int ni = 0; ni < NI; ni++)
            #pragma unroll
            for (int e = 0; e < 4; e++) c[mi][ni][e] = 0.f;

    float4 fa[4], fb[BI];

    // ---- prologue: load + store chunk 0 ----
    #pragma unroll
    for (int i = 0; i < 4; i++)
        fa[i] = *(const float4*)(A + (long long)(m0 + ar + i * 32) * lda + aq * 4);
    #pragma unroll
    for (int i = 0; i < BI; i++)
        fb[i] = *(const float4*)(B + (long long)(n0 + ar + i * 32) * ldb + aq * 4);
    #pragma unroll
    for (int i = 0; i < 4; i++) {
        int r = ar + i * 32, kp = aq * 2;
        As[0][swz(kp + 0, r, AW)] = pack_h2(fa[i].x, fa[i].y);
        As[0][swz(kp + 1, r, AW)] = pack_h2(fa[i].z, fa[i].w);
    }
    #pragma unroll
    for (int i = 0; i < BI; i++) {
        int r = ar + i * 32, kp = aq * 2;
        Bs[0][swz(kp + 0, r, BW)] = pack_h2(fb[i].x, fb[i].y);
        Bs[0][swz(kp + 1, r, BW)] = pack_h2(fb[i].z, fb[i].w);
    }
    __syncthreads();

    const int nch = K >> 5;
    for (int ch = 0; ch < nch; ch++) {
        const int buf = ch & 1;
        // prefetch next chunk to regs
        if (ch + 1 < nch) {
            const int kt = (ch + 1) * 32;
            #pragma unroll
            for (int i = 0; i < 4; i++)
                fa[i] = *(const float4*)(A + (long long)(m0 + ar + i * 32) * lda + kt + aq * 4);
            #pragma unroll
            for (int i = 0; i < BI; i++)
                fb[i] = *(const float4*)(B + (long long)(n0 + ar + i * 32) * ldb + kt + aq * 4);
        }
        // compute current chunk: 2 ks-steps of K=16
        const uint32_t* Ab = As[buf];
        const uint32_t* Bb = Bs[buf];
        #pragma unroll
        for (int ks = 0; ks < 2; ks++) {
            uint32_t a[4][4], b[NI][2];
            const int kp0 = ks * 8 + tig;
            #pragma unroll
            for (int mi = 0; mi < 4; mi++) {
                const int row = warpm * 64 + mi * 16 + gid;
                a[mi][0] = Ab[swz(kp0,     row,     AW)];
                a[mi][1] = Ab[swz(kp0,     row + 8, AW)];
                a[mi][2] = Ab[swz(kp0 + 4, row,     AW)];
                a[mi][3] = Ab[swz(kp0 + 4, row + 8, AW)];
            }
            #pragma unroll
            for (int ni = 0; ni < NI; ni++) {
                const int col = warpn * WN + ni * 8 + gid;
                b[ni][0] = Bb[swz(kp0,     col, BW)];
                b[ni][1] = Bb[swz(kp0 + 4, col, BW)];
            }
            #pragma unroll
            for (int mi = 0; mi < 4; mi++)
                #pragma unroll
                for (int ni = 0; ni < NI; ni++)
                    mma_f16(c[mi][ni], a[mi], b[ni]);
        }
        // store next chunk
        if (ch + 1 < nch) {
            uint32_t* An = As[buf ^ 1];
            uint32_t* Bn = Bs[buf ^ 1];
            #pragma unroll
            for (int i = 0; i < 4; i++) {
                int r = ar + i * 32, kp = aq * 2;
                An[swz(kp + 0, r, AW)] = pack_h2(fa[i].x, fa[i].y);
                An[swz(kp + 1, r, AW)] = pack_h2(fa[i].z, fa[i].w);
            }
            #pragma unroll
            for (int i = 0; i < BI; i++) {
                int r = ar + i * 32, kp = aq * 2;
                Bn[swz(kp + 0, r, BW)] = pack_h2(fb[i].x, fb[i].y);
                Bn[swz(kp + 1, r, BW)] = pack_h2(fb[i].z, fb[i].w);
            }
        }
        __syncthreads();
    }

    // ------------------------------ epilogue --------------------------------
    #pragma unroll
    for (int mi = 0; mi < 4; mi++) {
        #pragma unroll
        for (int ni = 0; ni < NI; ni++) {
            const int col = n0 + warpn * WN + ni * 8 + 2 * tig;
            float bx = 0.f, by = 0.f;
            if (bias) { bx = bias[col]; by = bias[col + 1]; }
            #pragma unroll
            for (int h = 0; h < 2; h++) {
                const int row = m0 + warpm * 64 + mi * 16 + gid + h * 8;
                float v0 = c[mi][ni][2*h + 0] * alpha + bx;
                float v1 = c[mi][ni][2*h + 1] * alpha + by;
                if (act == 1) {
                    v0 = 0.5f * v0 * (1.0f + erff(v0 * 0.70710678118654752f));
                    v1 = 0.5f * v1 * (1.0f + erff(v1 * 0.70710678118654752f));
                } else if (act == 2) {
                    v0 = fmaxf(v0, 0.f); v1 = fmaxf(v1, 0.f);
                } else if (act == 3) {
                    v0 = 1.f / (1.f + expf(-v0)); v1 = 1.f / (1.f + expf(-v1));
                }
                const long long g = (long long)row * ldc + col;
                if (resid) {
                    float2 q = *(const float2*)(resid + g);
                    v0 += q.x; v1 += q.y;
                }
                float2 o; o.x = v0; o.y = v1;
                *(float2*)(C + g) = o;
            }
        }
    }
}

// ---------------------------- batched transpose -----------------------------
__global__ __launch_bounds__(256)
void transpose_kernel(const float* __restrict__ in, int ldi, long long oI1, long long oI2,
                      float* __restrict__ out, int ldo, long long oO1, long long oO2,
                      int zdiv)
{
    const int z = blockIdx.z, zb = z / zdiv, zr = z - zb * zdiv;
    in  += zb * oI1 + zr * oI2;
    out += zb * oO1 + zr * oO2;
    __shared__ float t[32][33];
    const int r0 = blockIdx.y * 32, c0 = blockIdx.x * 32;
    const int tx = threadIdx.x & 31, ty = threadIdx.x >> 5;
    #pragma unroll
    for (int i = 0; i < 32; i += 8)
        t[ty + i][tx] = in[(long long)(r0 + ty + i) * ldi + c0 + tx];
    __syncthreads();
    #pragma unroll
    for (int i = 0; i < 32; i += 8)
        out[(long long)(c0 + ty + i) * ldo + r0 + tx] = t[tx][ty + i];
}

// ----------------------------- softmax rows --------------------------------
__global__ __launch_bounds__(128)
void softmax_kernel(float* __restrict__ S)
{
    float* row = S + (long long)blockIdx.x * 1024;
    const int t = threadIdx.x;
    float4 v0 = *(float4*)(row + t * 4);
    float4 v1 = *(float4*)(row + 512 + t * 4);

    __shared__ float sm[4];
    const int lane = t & 31, w = t >> 5;

    float m = fmaxf(fmaxf(fmaxf(v0.x, v0.y), fmaxf(v0.z, v0.w)),
                    fmaxf(fmaxf(v1.x, v1.y), fmaxf(v1.z, v1.w)));
    #pragma unroll
    for (int o = 16; o; o >>= 1) m = fmaxf(m, __shfl_xor_sync(0xffffffffu, m, o));
    if (lane == 0) sm[w] = m;
    __syncthreads();
    m = fmaxf(fmaxf(sm[0], sm[1]), fmaxf(sm[2], sm[3]));
    __syncthreads();

    v0.x = expf(v0.x - m); v0.y = expf(v0.y - m); v0.z = expf(v0.z - m); v0.w = expf(v0.w - m);
    v1.x = expf(v1.x - m); v1.y = expf(v1.y - m); v1.z = expf(v1.z - m); v1.w = expf(v1.w - m);

    float s = v0.x + v0.y + v0.z + v0.w + v1.x + v1.y + v1.z + v1.w;
    #pragma unroll
    for (int o = 16; o; o >>= 1) s += __shfl_xor_sync(0xffffffffu, s, o);
    if (lane == 0) sm[w] = s;
    __syncthreads();
    s = sm[0] + sm[1] + sm[2] + sm[3];
    const float inv = 1.f / s;

    v0.x *= inv; v0.y *= inv; v0.z *= inv; v0.w *= inv;
    v1.x *= inv; v1.y *= inv; v1.z *= inv; v1.w *= inv;
    *(float4*)(row + t * 4)       = v0;
    *(float4*)(row + 512 + t * 4) = v1;
}

// -------------------------- block reduce (256 thr) --------------------------
__device__ __forceinline__ float blk_sum256(float v)
{
    __shared__ float sm[8];
    const int lane = threadIdx.x & 31, w = threadIdx.x >> 5;
    #pragma unroll
    for (int o = 16; o; o >>= 1) v += __shfl_xor_sync(0xffffffffu, v, o);
    if (lane == 0) sm[w] = v;
    __syncthreads();
    if (w == 0) {
        float r = (lane < 8) ? sm[lane] : 0.f;
        #pragma unroll
        for (int o = 4; o; o >>= 1) r += __shfl_xor_sync(0xffffffffu, r, o);
        if (lane == 0) sm[0] = r;
    }
    __syncthreads();
    float r = sm[0];
    __syncthreads();
    return r;
}

// ------------------------------- adaLN --------------------------------------
__global__ __launch_bounds__(256)
void ada_ln_kernel(const float* __restrict__ in, const float* __restrict__ vol,
                   const float* __restrict__ w, const float* __restrict__ b,
                   const float* __restrict__ gamma, const float* __restrict__ beta,
                   const float* __restrict__ vsw, const float* __restrict__ vsb,
                   float* __restrict__ out)
{
    const long long row = blockIdx.x;
    const int t = threadIdx.x;
    float4 v = *(const float4*)(in + row * 1024 + t * 4);

    float mu = blk_sum256(v.x + v.y + v.z + v.w) * (1.f / 1024.f);
    float dx = v.x - mu, dy = v.y - mu, dz = v.z - mu, dw = v.w - mu;
    float var = blk_sum256(dx * dx + dy * dy + dz * dz + dw * dw) * (1.f / 1024.f);
    float inv = rsqrtf(var + 1e-5f);

    float vs = 1.f / (1.f + expf(-(vol[row] * (*vsw) + (*vsb))));
    float k1 = (1.f + vs) * (*gamma);
    float k0 = *beta;

    float4 w4 = *(const float4*)(w + t * 4);
    float4 b4 = *(const float4*)(b + t * 4);
    float4 o;
    o.x = (dx * inv * w4.x + b4.x) * k1 + k0;
    o.y = (dy * inv * w4.y + b4.y) * k1 + k0;
    o.z = (dz * inv * w4.z + b4.z) * k1 + k0;
    o.w = (dw * inv * w4.w + b4.w) * k1 + k0;
    *(float4*)(out + row * 1024 + t * 4) = o;
}

// -------- combine (x1*(2-g) + ffn*g) then adaLN2 -> out ----------------------
__global__ __launch_bounds__(256)
void combine_ada_ln_kernel(const float* __restrict__ x1, const float* __restrict__ f,
                           const float* __restrict__ g,  const float* __restrict__ vol,
                           const float* __restrict__ w,  const float* __restrict__ b,
                           const float* __restrict__ gamma, const float* __restrict__ beta,
                           const float* __restrict__ vsw, const float* __restrict__ vsb,
                           float* __restrict__ out)
{
    const long long row = blockIdx.x;
    const int t = threadIdx.x;
    float4 a  = *(const float4*)(x1 + row * 1024 + t * 4);
    float4 ff = *(const float4*)(f  + row * 1024 + t * 4);
    float4 gg = *(const float4*)(g  + row * 1024 + t * 4);

    float4 v;
    v.x = a.x * (2.f - gg.x) + ff.x * gg.x;
    v.y = a.y * (2.f - gg.y) + ff.y * gg.y;
    v.z = a.z * (2.f - gg.z) + ff.z * gg.z;
    v.w = a.w * (2.f - gg.w) + ff.w * gg.w;

    float mu = blk_sum256(v.x + v.y + v.z + v.w) * (1.f / 1024.f);
    float dx = v.x - mu, dy = v.y - mu, dz = v.z - mu, dw = v.w - mu;
    float var = blk_sum256(dx * dx + dy * dy + dz * dz + dw * dw) * (1.f / 1024.f);
    float inv = rsqrtf(var + 1e-5f);

    float vs = 1.f / (1.f + expf(-(vol[row] * (*vsw) + (*vsb))));
    float k1 = (1.f + vs) * (*gamma);
    float k0 = *beta;

    float4 w4 = *(const float4*)(w + t * 4);
    float4 b4 = *(const float4*)(b + t * 4);
    float4 o;
    o.x = (dx * inv * w4.x + b4.x) * k1 + k0;
    o.y = (dy * inv * w4.y + b4.y) * k1 + k0;
    o.z = (dz * inv * w4.z + b4.z) * k1 + k0;
    o.w = (dw * inv * w4.w + b4.w) * k1 + k0;
    *(float4*)(out + row * 1024 + t * 4) = o;
}

// ------------------------------ launcher ------------------------------------
#define SMEM_G128 (2 * (16*128 + 16*128) * 4)   // 32768
#define SMEM_G64  (2 * (16*128 + 16*64)  * 4)   // 24576

extern "C" void kernel_launch(void* const* d_in, const int* in_sizes, int n_in,
                              void* d_out, int out_size)
{
    const float* x      = (const float*)d_in[0];
    const float* vol    = (const float*)d_in[1];
    const float* Wq     = (const float*)d_in[2];
    const float* bq     = (const float*)d_in[3];
    const float* Wk     = (const float*)d_in[4];
    const float* bk     = (const float*)d_in[5];
    const float* Wv     = (const float*)d_in[6];
    const float* bv     = (const float*)d_in[7];
    const float* Wo     = (const float*)d_in[8];
    const float* bo     = (const float*)d_in[9];
    const float* ln1w   = (const float*)d_in[10];
    const float* ln1b   = (const float*)d_in[11];
    const float* gamma1 = (const float*)d_in[12];
    const float* beta1  = (const float*)d_in[13];
    const float* vs1w   = (const float*)d_in[14];
    const float* vs1b   = (const float*)d_in[15];
    const float* fw1    = (const float*)d_in[16];
    const float* fb1    = (const float*)d_in[17];
    const float* fw2    = (const float*)d_in[18];
    const float* fb2    = (const float*)d_in[19];
    const float* gw1    = (const float*)d_in[20];
    const float* gb1    = (const float*)d_in[21];
    const float* gw2    = (const float*)d_in[22];
    const float* gb2    = (const float*)d_in[23];
    const float* ln2w   = (const float*)d_in[24];
    const float* ln2b   = (const float*)d_in[25];
    const float* gamma2 = (const float*)d_in[26];
    const float* beta2  = (const float*)d_in[27];
    const float* vs2w   = (const float*)d_in[28];
    const float* vs2b   = (const float*)d_in[29];
    float* out = (float*)d_out;

    float *Q, *Kb, *Vb, *Vt, *Sb, *ctx, *xr, *x1, *h, *f, *g1, *g;
    float *WqT, *WkT, *WvT, *WoT, *fw1T, *fw2T, *gw1T, *gw2T;
    cudaGetSymbolAddress((void**)&Q,    g_Q);
    cudaGetSymbolAddress((void**)&Kb,   g_K);
    cudaGetSymbolAddress((void**)&Vb,   g_V);
    cudaGetSymbolAddress((void**)&Vt,   g_Vt);
    cudaGetSymbolAddress((void**)&Sb,   g_S);
    cudaGetSymbolAddress((void**)&ctx,  g_ctx);
    cudaGetSymbolAddress((void**)&xr,   g_xr);
    cudaGetSymbolAddress((void**)&x1,   g_x1);
    cudaGetSymbolAddress((void**)&h,    g_h);
    cudaGetSymbolAddress((void**)&f,    g_f);
    cudaGetSymbolAddress((void**)&g1,   g_g1);
    cudaGetSymbolAddress((void**)&g,    g_g);
    cudaGetSymbolAddress((void**)&WqT,  g_WqT);
    cudaGetSymbolAddress((void**)&WkT,  g_WkT);
    cudaGetSymbolAddress((void**)&WvT,  g_WvT);
    cudaGetSymbolAddress((void**)&WoT,  g_WoT);
    cudaGetSymbolAddress((void**)&fw1T, g_fw1T);
    cudaGetSymbolAddress((void**)&fw2T, g_fw2T);
    cudaGetSymbolAddress((void**)&gw1T, g_gw1T);
    cudaGetSymbolAddress((void**)&gw2T, g_gw2T);

    cudaFuncSetAttribute(mma_gemm<128>, cudaFuncAttributeMaxDynamicSharedMemorySize, SMEM_G128);
    cudaFuncSetAttribute(mma_gemm<64>,  cudaFuncAttributeMaxDynamicSharedMemorySize, SMEM_G64);

    const long long SH = (long long)Ssz * Hsz;      // 1048576
    const long long SS = (long long)Ssz * Ssz;      // 1048576

    // ---- weight transposes (W[K,N] -> WT[N,K]) ----
    transpose_kernel<<<dim3(Hsz/32, Hsz/32, 1), 256>>>(Wq, Hsz, 0,0, WqT, Hsz, 0,0, 1);
    transpose_kernel<<<dim3(Hsz/32, Hsz/32, 1), 256>>>(Wk, Hsz, 0,0, WkT, Hsz, 0,0, 1);
    transpose_kernel<<<dim3(Hsz/32, Hsz/32, 1), 256>>>(Wv, Hsz, 0,0, WvT, Hsz, 0,0, 1);
    transpose_kernel<<<dim3(Hsz/32, Hsz/32, 1), 256>>>(Wo, Hsz, 0,0, WoT, Hsz, 0,0, 1);
    transpose_kernel<<<dim3(HF/32,  Hsz/32, 1), 256>>>(fw1, HF, 0,0, fw1T, Hsz, 0,0, 1);
    transpose_kernel<<<dim3(Hsz/32, HF/32,  1), 256>>>(fw2, Hsz, 0,0, fw2T, HF, 0,0, 1);
    transpose_kernel<<<dim3(HG/32,  Hsz/32, 1), 256>>>(gw1, HG, 0,0, gw1T, Hsz, 0,0, 1);
    transpose_kernel<<<dim3(Hsz/32, HG/32,  1), 256>>>(gw2, Hsz, 0,0, gw2T, HG, 0,0, 1);

    // ---- QKV projections ----
    mma_gemm<128><<<dim3(8,64,1),256,SMEM_G128>>>(x,Hsz,0,0, WqT,Hsz,0,0, Q,Hsz,0,0, bq,nullptr, Hsz,1, 1.f,0);
    mma_gemm<128><<<dim3(8,64,1),256,SMEM_G128>>>(x,Hsz,0,0, WkT,Hsz,0,0, Kb,Hsz,0,0, bk,nullptr, Hsz,1, 1.f,0);
    mma_gemm<128><<<dim3(8,64,1),256,SMEM_G128>>>(x,Hsz,0,0, WvT,Hsz,0,0, Vb,Hsz,0,0, bv,nullptr, Hsz,1, 1.f,0);

    // ---- scores = Q @ K^T / 8 (batched over b,h) ----
    mma_gemm<128><<<dim3(8,8,Bsz*NH),256,SMEM_G128>>>(Q,Hsz,SH,HD, Kb,Hsz,SH,HD,
                                                      Sb,Ssz,(long long)NH*SS,SS,
                                                      nullptr,nullptr, HD,NH, 0.125f,0);
    // ---- softmax ----
    softmax_kernel<<<Bsz*NH*Ssz,128>>>(Sb);

    // ---- V permute: Vt[b,h,d,s] = V[b,s,h*64+d] ----
    transpose_kernel<<<dim3(2,32,Bsz*NH),256>>>(Vb, Hsz, SH, HD,
                                                Vt, Ssz, (long long)NH*HD*Ssz, (long long)HD*Ssz, NH);

    // ---- ctx = attn @ V ----
    mma_gemm<64><<<dim3(1,8,Bsz*NH),256,SMEM_G64>>>(Sb,Ssz,(long long)NH*SS,SS,
                                                    Vt,Ssz,(long long)NH*HD*Ssz,(long long)HD*Ssz,
                                                    ctx,Hsz,SH,HD,
                                                    nullptr,nullptr, Ssz,NH, 1.f,0);

    // ---- O projection + residual ----
    mma_gemm<128><<<dim3(8,64,1),256,SMEM_G128>>>(ctx,Hsz,0,0, WoT,Hsz,0,0, xr,Hsz,0,0, bo,x, Hsz,1, 1.f,0);

    // ---- adaLN1 ----
    ada_ln_kernel<<<Mrows,256>>>(xr, vol, ln1w, ln1b, gamma1, beta1, vs1w, vs1b, x1);

    // ---- FFN ----
    mma_gemm<128><<<dim3(32,64,1),256,SMEM_G128>>>(x1,Hsz,0,0, fw1T,Hsz,0,0, h,HF,0,0,  fb1,nullptr, Hsz,1, 1.f,1);
    mma_gemm<128><<<dim3(8,64,1), 256,SMEM_G128>>>(h,HF,0,0,  fw2T,HF,0,0,  f,Hsz,0,0,  fb2,nullptr, HF,1,  1.f,0);

    // ---- gate ----
    mma_gemm<128><<<dim3(4,64,1),256,SMEM_G128>>>(x1,Hsz,0,0, gw1T,Hsz,0,0, g1,HG,0,0, gb1,nullptr, Hsz,1, 1.f,2);
    mma_gemm<128><<<dim3(8,64,1),256,SMEM_G128>>>(g1,HG,0,0,  gw2T,HG,0,0,  g,Hsz,0,0, gb2,nullptr, HG,1,  1.f,3);

    // ---- combine + adaLN2 -> out ----
    combine_ada_ln_kernel<<<Mrows,256>>>(x1, f, g, vol, ln2w, ln2b, gamma2, beta2, vs2w, vs2b, out);
}

// round 5
// speedup vs baseline: 3.9013x; 1.4635x over previous
#include <cuda_runtime.h>
#include <cuda_bf16.h>
#include <cuda_fp16.h>
#include <math.h>
#include <stdint.h>

// ---------------------------------------------------------------------------
// EnhancedTransformerBlock  B=8 S=1024 H=1024 nh=16 hd=64
// fp16 mma.sync GEMMs + fused flash-attention + fused elementwise
// ---------------------------------------------------------------------------

#define Bsz   8
#define Ssz   1024
#define Hsz   1024
#define NH    16
#define HD    64
#define Mrows (Bsz*Ssz)          // 8192
#define HF    (4*Hsz)            // 4096
#define HG    (Hsz/2)            // 512

// ------------------------- scratch (device globals) ------------------------
__device__ __half g_Qh [(size_t)Mrows*Hsz];
__device__ __half g_Kh [(size_t)Mrows*Hsz];
__device__ __half g_Vh [(size_t)Mrows*Hsz];
__device__ __half g_ctx[(size_t)Mrows*Hsz];
__device__ float  g_xr [(size_t)Mrows*Hsz];
__device__ float  g_x1 [(size_t)Mrows*Hsz];
__device__ __half g_h  [(size_t)Mrows*HF];
__device__ float  g_f  [(size_t)Mrows*Hsz];
__device__ __half g_g1 [(size_t)Mrows*HG];
__device__ float  g_g  [(size_t)Mrows*Hsz];
// transposed fp16 weights ([N][K] K-major)
__device__ __half g_WqT [(size_t)Hsz*Hsz];
__device__ __half g_WkT [(size_t)Hsz*Hsz];
__device__ __half g_WvT [(size_t)Hsz*Hsz];
__device__ __half g_WoT [(size_t)Hsz*Hsz];
__device__ __half g_fw1T[(size_t)Hsz*HF];
__device__ __half g_fw2T[(size_t)HF*Hsz];
__device__ __half g_gw1T[(size_t)Hsz*HG];
__device__ __half g_gw2T[(size_t)HG*Hsz];

// ------------------------------ helpers ------------------------------------
__device__ __forceinline__ uint32_t pack_h2(float lo, float hi) {
    __half2 h = __floats2half2_rn(lo, hi);
    return *(uint32_t*)&h;
}
__device__ __forceinline__ void mma_f16(float* c, const uint32_t* a, const uint32_t* b) {
    asm volatile(
        "mma.sync.aligned.m16n8k16.row.col.f32.f16.f16.f32 "
        "{%0,%1,%2,%3}, {%4,%5,%6,%7}, {%8,%9}, {%0,%1,%2,%3};"
        : "+f"(c[0]), "+f"(c[1]), "+f"(c[2]), "+f"(c[3])
        : "r"(a[0]), "r"(a[1]), "r"(a[2]), "r"(a[3]), "r"(b[0]), "r"(b[1]));
}
// [16 kp][W] half2-word tile swizzle (bank-conflict-free staging + frag loads)
__device__ __forceinline__ int swz(int kp, int m, int W) {
    return kp * W + (m ^ ((kp & 3) << 3) ^ (((kp >> 2) & 7) << 2));
}
__device__ __forceinline__ int sw128(int byte) {       // SW128 byte swizzle
    return byte ^ ((byte >> 3) & 0x70);
}
__device__ __forceinline__ uint32_t smem_addr(const void* p) {
    return (uint32_t)__cvta_generic_to_shared(p);
}

// ----------------------------- FP16 GEMM -----------------------------------
// C[m,n] = act((sum_k A[m,k]*B[n,k] + bias[n]) * alpha) (+resid)
// A: [M,K] K-major (AT = float|__half), B: fp16 [N,K] K-major, C: CT.
template<int NT, typename AT, typename CT>
__global__ __launch_bounds__(256)
void mma_gemm(const AT* __restrict__ A, int lda,
              const __half* __restrict__ B, int ldb,
              CT* __restrict__ C, int ldc,
              const float* __restrict__ bias, const float* __restrict__ resid,
              int K, float alpha, int act)
{
    constexpr int BI = NT / 32;
    constexpr int NI = NT / 32;
    constexpr int WN = NT / 4;
    constexpr int AW = 128, BW = NT;
    constexpr bool AH = (sizeof(AT) == 2);

    extern __shared__ uint32_t smem[];
    uint32_t* As[2] = { smem,             smem + 16 * 128 };
    uint32_t* Bs[2] = { smem + 32 * 128,  smem + 32 * 128 + 16 * NT };

    const int tid = threadIdx.x, wid = tid >> 5, lane = tid & 31;
    const int gid = lane >> 2, tig = lane & 3;
    const int warpm = wid & 1, warpn = wid >> 1;

    const int m0 = blockIdx.y * 128;
    const int n0 = blockIdx.x * NT;
    const int ar = tid >> 3, aq = tid & 7;

    float c[4][NI][4];
    #pragma unroll
    for (int mi = 0; mi < 4; mi++)
        #pragma unroll
        for (int ni = 0; ni < NI; ni++)
            #pragma unroll
            for (int e = 0; e < 4; e++) c[mi][ni][e] = 0.f;

    float4 fa[4]; uint2 ha[4]; uint2 hb[BI];

    // ---- prologue: chunk 0 ----
    #pragma unroll
    for (int i = 0; i < 4; i++) {
        if (AH) ha[i] = *(const uint2*)((const __half*)A + (long long)(m0 + ar + i * 32) * lda + aq * 4);
        else    fa[i] = *(const float4*)((const float*)A + (long long)(m0 + ar + i * 32) * lda + aq * 4);
    }
    #pragma unroll
    for (int i = 0; i < BI; i++)
        hb[i] = *(const uint2*)(B + (long long)(n0 + ar + i * 32) * ldb + aq * 4);
    #pragma unroll
    for (int i = 0; i < 4; i++) {
        int r = ar + i * 32, kp = aq * 2;
        if (AH) { As[0][swz(kp, r, AW)] = ha[i].x; As[0][swz(kp + 1, r, AW)] = ha[i].y; }
        else    { As[0][swz(kp, r, AW)] = pack_h2(fa[i].x, fa[i].y);
                  As[0][swz(kp + 1, r, AW)] = pack_h2(fa[i].z, fa[i].w); }
    }
    #pragma unroll
    for (int i = 0; i < BI; i++) {
        int r = ar + i * 32, kp = aq * 2;
        Bs[0][swz(kp, r, BW)] = hb[i].x;
        Bs[0][swz(kp + 1, r, BW)] = hb[i].y;
    }
    __syncthreads();

    const int nch = K >> 5;
    for (int ch = 0; ch < nch; ch++) {
        const int buf = ch & 1;
        if (ch + 1 < nch) {
            const int kt = (ch + 1) * 32;
            #pragma unroll
            for (int i = 0; i < 4; i++) {
                if (AH) ha[i] = *(const uint2*)((const __half*)A + (long long)(m0 + ar + i * 32) * lda + kt + aq * 4);
                else    fa[i] = *(const float4*)((const float*)A + (long long)(m0 + ar + i * 32) * lda + kt + aq * 4);
            }
            #pragma unroll
            for (int i = 0; i < BI; i++)
                hb[i] = *(const uint2*)(B + (long long)(n0 + ar + i * 32) * ldb + kt + aq * 4);
        }
        const uint32_t* Ab = As[buf];
        const uint32_t* Bb = Bs[buf];
        #pragma unroll
        for (int ks = 0; ks < 2; ks++) {
            uint32_t a[4][4], b[NI][2];
            const int kp0 = ks * 8 + tig;
            #pragma unroll
            for (int mi = 0; mi < 4; mi++) {
                const int row = warpm * 64 + mi * 16 + gid;
                a[mi][0] = Ab[swz(kp0,     row,     AW)];
                a[mi][1] = Ab[swz(kp0,     row + 8, AW)];
                a[mi][2] = Ab[swz(kp0 + 4, row,     AW)];
                a[mi][3] = Ab[swz(kp0 + 4, row + 8, AW)];
            }
            #pragma unroll
            for (int ni = 0; ni < NI; ni++) {
                const int col = warpn * WN + ni * 8 + gid;
                b[ni][0] = Bb[swz(kp0,     col, BW)];
                b[ni][1] = Bb[swz(kp0 + 4, col, BW)];
            }
            #pragma unroll
            for (int mi = 0; mi < 4; mi++)
                #pragma unroll
                for (int ni = 0; ni < NI; ni++)
                    mma_f16(c[mi][ni], a[mi], b[ni]);
        }
        if (ch + 1 < nch) {
            uint32_t* An = As[buf ^ 1];
            uint32_t* Bn = Bs[buf ^ 1];
            #pragma unroll
            for (int i = 0; i < 4; i++) {
                int r = ar + i * 32, kp = aq * 2;
                if (AH) { An[swz(kp, r, AW)] = ha[i].x; An[swz(kp + 1, r, AW)] = ha[i].y; }
                else    { An[swz(kp, r, AW)] = pack_h2(fa[i].x, fa[i].y);
                          An[swz(kp + 1, r, AW)] = pack_h2(fa[i].z, fa[i].w); }
            }
            #pragma unroll
            for (int i = 0; i < BI; i++) {
                int r = ar + i * 32, kp = aq * 2;
                Bn[swz(kp, r, BW)] = hb[i].x;
                Bn[swz(kp + 1, r, BW)] = hb[i].y;
            }
        }
        __syncthreads();
    }

    // ------------------------------ epilogue --------------------------------
    #pragma unroll
    for (int mi = 0; mi < 4; mi++) {
        #pragma unroll
        for (int ni = 0; ni < NI; ni++) {
            const int col = n0 + warpn * WN + ni * 8 + 2 * tig;
            float bx = 0.f, by = 0.f;
            if (bias) { bx = bias[col]; by = bias[col + 1]; }
            #pragma unroll
            for (int h = 0; h < 2; h++) {
                const int row = m0 + warpm * 64 + mi * 16 + gid + h * 8;
                float v0 = (c[mi][ni][2*h + 0] + bx) * alpha;
                float v1 = (c[mi][ni][2*h + 1] + by) * alpha;
                if (act == 1) {
                    v0 = 0.5f * v0 * (1.0f + erff(v0 * 0.70710678118654752f));
                    v1 = 0.5f * v1 * (1.0f + erff(v1 * 0.70710678118654752f));
                } else if (act == 2) {
                    v0 = fmaxf(v0, 0.f); v1 = fmaxf(v1, 0.f);
                } else if (act == 3) {
                    v0 = 1.f / (1.f + expf(-v0)); v1 = 1.f / (1.f + expf(-v1));
                }
                const long long g = (long long)row * ldc + col;
                if (sizeof(CT) == 2) {
                    *(__half2*)((__half*)C + g) = __floats2half2_rn(v0, v1);
                } else {
                    if (resid) {
                        float2 q = *(const float2*)(resid + g);
                        v0 += q.x; v1 += q.y;
                    }
                    float2 o; o.x = v0; o.y = v1;
                    *(float2*)((float*)C + g) = o;
                }
            }
        }
    }
}

// ----------------------- fused flash attention ------------------------------
// ctx[b, q, h*64+d] = softmax(Q K^T) V   (scale pre-folded into Q)
// grid: (8 q-tiles, B*NH); 256 threads; K-tile = 64
__global__ __launch_bounds__(256)
void flash_attn(const __half* __restrict__ Qh, const __half* __restrict__ Kh,
                const __half* __restrict__ Vh, __half* __restrict__ ctx)
{
    __shared__ __align__(128) char sm[(128 + 64 + 64) * 128];
    char* Qs = sm;
    char* Ks = sm + 128 * 128;
    char* Vs = sm + 192 * 128;

    const int tid = threadIdx.x, wid = tid >> 5, lane = tid & 31;
    const int gid = lane >> 2, tig = lane & 3;
    const int qt = blockIdx.x, bh = blockIdx.y;
    const int b = bh >> 4, hh = bh & 15;

    const __half* Qg = Qh + ((size_t)(b * 1024 + qt * 128) * 1024 + hh * 64);
    const __half* Kg = Kh + ((size_t)b * 1024 * 1024 + hh * 64);
    const __half* Vg = Vh + ((size_t)b * 1024 * 1024 + hh * 64);

    // stage Q (128 x 64 half, SW128)
    #pragma unroll
    for (int i = 0; i < 4; i++) {
        int id = tid + i * 256;
        int r = id >> 3, cc = id & 7;
        uint4 u = *(const uint4*)(Qg + (size_t)r * 1024 + cc * 8);
        *(uint4*)(Qs + sw128(r * 128 + cc * 16)) = u;
    }
    __syncthreads();

    // persistent Q a-frags: qf[ks][0..3], ks = d-chunk of 16
    uint32_t qf[4][4];
    #pragma unroll
    for (int ks = 0; ks < 4; ks++) {
        int row = wid * 16 + (lane & 15);
        int colb = ks * 32 + ((lane & 16) ? 16 : 0);
        uint32_t addr = smem_addr(Qs + sw128(row * 128 + colb));
        asm volatile("ldmatrix.sync.aligned.m8n8.x4.shared.b16 {%0,%1,%2,%3}, [%4];"
            : "=r"(qf[ks][0]), "=r"(qf[ks][1]), "=r"(qf[ks][2]), "=r"(qf[ks][3]) : "r"(addr));
    }

    float m0 = -1e30f, m1 = -1e30f, l0 = 0.f, l1 = 0.f;
    float o[8][4];
    #pragma unroll
    for (int nt = 0; nt < 8; nt++)
        #pragma unroll
        for (int e = 0; e < 4; e++) o[nt][e] = 0.f;

    for (int kt = 0; kt < 16; kt++) {
        __syncthreads();
        #pragma unroll
        for (int i = 0; i < 2; i++) {
            int id = tid + i * 256;
            int r = id >> 3, cc = id & 7;
            uint4 uk = *(const uint4*)(Kg + (size_t)(kt * 64 + r) * 1024 + cc * 8);
            uint4 uv = *(const uint4*)(Vg + (size_t)(kt * 64 + r) * 1024 + cc * 8);
            int swb = sw128(r * 128 + cc * 16);
            *(uint4*)(Ks + swb) = uk;
            *(uint4*)(Vs + swb) = uv;
        }
        __syncthreads();

        // ---- S = Q @ K^T ----
        float s[8][4];
        #pragma unroll
        for (int nt = 0; nt < 8; nt++)
            #pragma unroll
            for (int e = 0; e < 4; e++) s[nt][e] = 0.f;

        #pragma unroll
        for (int ks = 0; ks < 4; ks++) {
            uint32_t kb[8][2];
            #pragma unroll
            for (int ntp = 0; ntp < 4; ntp++) {
                int row = ntp * 16 + (lane & 7) + ((lane & 16) ? 8 : 0);
                int colb = ks * 32 + ((lane & 8) ? 16 : 0);
                uint32_t addr = smem_addr(Ks + sw128(row * 128 + colb));
                asm volatile("ldmatrix.sync.aligned.m8n8.x4.shared.b16 {%0,%1,%2,%3}, [%4];"
                    : "=r"(kb[2*ntp][0]), "=r"(kb[2*ntp][1]),
                      "=r"(kb[2*ntp+1][0]), "=r"(kb[2*ntp+1][1]) : "r"(addr));
            }
            #pragma unroll
            for (int nt = 0; nt < 8; nt++)
                mma_f16(s[nt], qf[ks], kb[nt]);
        }

        // ---- online softmax ----
        float mc0 = -1e30f, mc1 = -1e30f;
        #pragma unroll
        for (int nt = 0; nt < 8; nt++) {
            mc0 = fmaxf(mc0, fmaxf(s[nt][0], s[nt][1]));
            mc1 = fmaxf(mc1, fmaxf(s[nt][2], s[nt][3]));
        }
        mc0 = fmaxf(mc0, __shfl_xor_sync(0xffffffffu, mc0, 1));
        mc0 = fmaxf(mc0, __shfl_xor_sync(0xffffffffu, mc0, 2));
        mc1 = fmaxf(mc1, __shfl_xor_sync(0xffffffffu, mc1, 1));
        mc1 = fmaxf(mc1, __shfl_xor_sync(0xffffffffu, mc1, 2));
        float mn0 = fmaxf(m0, mc0), mn1 = fmaxf(m1, mc1);
        float sc0 = __expf(m0 - mn0), sc1 = __expf(m1 - mn1);
        m0 = mn0; m1 = mn1;

        float rs0 = 0.f, rs1 = 0.f;
        uint32_t pf[8][2];
        #pragma unroll
        for (int nt = 0; nt < 8; nt++) {
            float p0 = __expf(s[nt][0] - mn0);
            float p1 = __expf(s[nt][1] - mn0);
            float p2 = __expf(s[nt][2] - mn1);
            float p3 = __expf(s[nt][3] - mn1);
            rs0 += p0 + p1; rs1 += p2 + p3;
            pf[nt][0] = pack_h2(p0, p1);
            pf[nt][1] = pack_h2(p2, p3);
        }
        rs0 += __shfl_xor_sync(0xffffffffu, rs0, 1);
        rs0 += __shfl_xor_sync(0xffffffffu, rs0, 2);
        rs1 += __shfl_xor_sync(0xffffffffu, rs1, 1);
        rs1 += __shfl_xor_sync(0xffffffffu, rs1, 2);
        l0 = l0 * sc0 + rs0;
        l1 = l1 * sc1 + rs1;
        #pragma unroll
        for (int nt = 0; nt < 8; nt++) {
            o[nt][0] *= sc0; o[nt][1] *= sc0;
            o[nt][2] *= sc1; o[nt][3] *= sc1;
        }

        // ---- O += P @ V ----
        #pragma unroll
        for (int ks = 0; ks < 4; ks++) {
            uint32_t vb[8][2];
            #pragma unroll
            for (int ntp = 0; ntp < 4; ntp++) {
                int row = ks * 16 + (lane & 7) + ((lane & 8) ? 8 : 0);
                int colb = ntp * 32 + ((lane & 16) ? 16 : 0);
                uint32_t addr = smem_addr(Vs + sw128(row * 128 + colb));
                asm volatile("ldmatrix.sync.aligned.m8n8.x4.trans.shared.b16 {%0,%1,%2,%3}, [%4];"
                    : "=r"(vb[2*ntp][0]), "=r"(vb[2*ntp][1]),
                      "=r"(vb[2*ntp+1][0]), "=r"(vb[2*ntp+1][1]) : "r"(addr));
            }
            uint32_t a[4] = { pf[2*ks][0], pf[2*ks][1], pf[2*ks+1][0], pf[2*ks+1][1] };
            #pragma unroll
            for (int nt = 0; nt < 8; nt++)
                mma_f16(o[nt], a, vb[nt]);
        }
    }

    // ---- epilogue ----
    float inv0 = 1.f / l0, inv1 = 1.f / l1;
    const int row0 = b * 1024 + qt * 128 + wid * 16 + gid;
    #pragma unroll
    for (int nt = 0; nt < 8; nt++) {
        int col = hh * 64 + nt * 8 + 2 * tig;
        *(__half2*)(ctx + (size_t)row0 * 1024 + col) =
            __floats2half2_rn(o[nt][0] * inv0, o[nt][1] * inv0);
        *(__half2*)(ctx + (size_t)(row0 + 8) * 1024 + col) =
            __floats2half2_rn(o[nt][2] * inv1, o[nt][3] * inv1);
    }
}

// ------------------- weight transpose (fp32 -> fp16) ------------------------
__global__ __launch_bounds__(256)
void transpose_h_kernel(const float* __restrict__ in, int ldi,
                        __half* __restrict__ out, int ldo)
{
    __shared__ float t[32][33];
    const int r0 = blockIdx.y * 32, c0 = blockIdx.x * 32;
    const int tx = threadIdx.x & 31, ty = threadIdx.x >> 5;
    #pragma unroll
    for (int i = 0; i < 32; i += 8)
        t[ty + i][tx] = in[(long long)(r0 + ty + i) * ldi + c0 + tx];
    __syncthreads();
    #pragma unroll
    for (int i = 0; i < 32; i += 8)
        out[(long long)(c0 + ty + i) * ldo + r0 + tx] = __float2half(t[tx][ty + i]);
}

// -------------------------- block reduce (256 thr) --------------------------
__device__ __forceinline__ float blk_sum256(float v)
{
    __shared__ float sm[8];
    const int lane = threadIdx.x & 31, w = threadIdx.x >> 5;
    #pragma unroll
    for (int o = 16; o; o >>= 1) v += __shfl_xor_sync(0xffffffffu, v, o);
    if (lane == 0) sm[w] = v;
    __syncthreads();
    if (w == 0) {
        float r = (lane < 8) ? sm[lane] : 0.f;
        #pragma unroll
        for (int o = 4; o; o >>= 1) r += __shfl_xor_sync(0xffffffffu, r, o);
        if (lane == 0) sm[0] = r;
    }
    __syncthreads();
    float r = sm[0];
    __syncthreads();
    return r;
}

// ------------------------------- adaLN --------------------------------------
__global__ __launch_bounds__(256)
void ada_ln_kernel(const float* __restrict__ in, const float* __restrict__ vol,
                   const float* __restrict__ w, const float* __restrict__ b,
                   const float* __restrict__ gamma, const float* __restrict__ beta,
                   const float* __restrict__ vsw, const float* __restrict__ vsb,
                   float* __restrict__ out)
{
    const long long row = blockIdx.x;
    const int t = threadIdx.x;
    float4 v = *(const float4*)(in + row * 1024 + t * 4);

    float mu = blk_sum256(v.x + v.y + v.z + v.w) * (1.f / 1024.f);
    float dx = v.x - mu, dy = v.y - mu, dz = v.z - mu, dw = v.w - mu;
    float var = blk_sum256(dx * dx + dy * dy + dz * dz + dw * dw) * (1.f / 1024.f);
    float inv = rsqrtf(var + 1e-5f);

    float vs = 1.f / (1.f + expf(-(vol[row] * (*vsw) + (*vsb))));
    float k1 = (1.f + vs) * (*gamma);
    float k0 = *beta;

    float4 w4 = *(const float4*)(w + t * 4);
    float4 b4 = *(const float4*)(b + t * 4);
    float4 o;
    o.x = (dx * inv * w4.x + b4.x) * k1 + k0;
    o.y = (dy * inv * w4.y + b4.y) * k1 + k0;
    o.z = (dz * inv * w4.z + b4.z) * k1 + k0;
    o.w = (dw * inv * w4.w + b4.w) * k1 + k0;
    *(float4*)(out + row * 1024 + t * 4) = o;
}

// -------- combine (x1*(2-g) + ffn*g) then adaLN2 -> out ----------------------
__global__ __launch_bounds__(256)
void combine_ada_ln_kernel(const float* __restrict__ x1, const float* __restrict__ f,
                           const float* __restrict__ g,  const float* __restrict__ vol,
                           const float* __restrict__ w,  const float* __restrict__ b,
                           const float* __restrict__ gamma, const float* __restrict__ beta,
                           const float* __restrict__ vsw, const float* __restrict__ vsb,
                           float* __restrict__ out)
{
    const long long row = blockIdx.x;
    const int t = threadIdx.x;
    float4 a  = *(const float4*)(x1 + row * 1024 + t * 4);
    float4 ff = *(const float4*)(f  + row * 1024 + t * 4);
    float4 gg = *(const float4*)(g  + row * 1024 + t * 4);

    float4 v;
    v.x = a.x * (2.f - gg.x) + ff.x * gg.x;
    v.y = a.y * (2.f - gg.y) + ff.y * gg.y;
    v.z = a.z * (2.f - gg.z) + ff.z * gg.z;
    v.w = a.w * (2.f - gg.w) + ff.w * gg.w;

    float mu = blk_sum256(v.x + v.y + v.z + v.w) * (1.f / 1024.f);
    float dx = v.x - mu, dy = v.y - mu, dz = v.z - mu, dw = v.w - mu;
    float var = blk_sum256(dx * dx + dy * dy + dz * dz + dw * dw) * (1.f / 1024.f);
    float inv = rsqrtf(var + 1e-5f);

    float vs = 1.f / (1.f + expf(-(vol[row] * (*vsw) + (*vsb))));
    float k1 = (1.f + vs) * (*gamma);
    float k0 = *beta;

    float4 w4 = *(const float4*)(w + t * 4);
    float4 b4 = *(const float4*)(b + t * 4);
    float4 o;
    o.x = (dx * inv * w4.x + b4.x) * k1 + k0;
    o.y = (dy * inv * w4.y + b4.y) * k1 + k0;
    o.z = (dz * inv * w4.z + b4.z) * k1 + k0;
    o.w = (dw * inv * w4.w + b4.w) * k1 + k0;
    *(float4*)(out + row * 1024 + t * 4) = o;
}

// ------------------------------ launcher ------------------------------------
#define SMEM_G128 (2 * (16*128 + 16*128) * 4)   // 32768

extern "C" void kernel_launch(void* const* d_in, const int* in_sizes, int n_in,
                              void* d_out, int out_size)
{
    const float* x      = (const float*)d_in[0];
    const float* vol    = (const float*)d_in[1];
    const float* Wq     = (const float*)d_in[2];
    const float* bq     = (const float*)d_in[3];
    const float* Wk     = (const float*)d_in[4];
    const float* bk     = (const float*)d_in[5];
    const float* Wv     = (const float*)d_in[6];
    const float* bv     = (const float*)d_in[7];
    const float* Wo     = (const float*)d_in[8];
    const float* bo     = (const float*)d_in[9];
    const float* ln1w   = (const float*)d_in[10];
    const float* ln1b   = (const float*)d_in[11];
    const float* gamma1 = (const float*)d_in[12];
    const float* beta1  = (const float*)d_in[13];
    const float* vs1w   = (const float*)d_in[14];
    const float* vs1b   = (const float*)d_in[15];
    const float* fw1    = (const float*)d_in[16];
    const float* fb1    = (const float*)d_in[17];
    const float* fw2    = (const float*)d_in[18];
    const float* fb2    = (const float*)d_in[19];
    const float* gw1    = (const float*)d_in[20];
    const float* gb1    = (const float*)d_in[21];
    const float* gw2    = (const float*)d_in[22];
    const float* gb2    = (const float*)d_in[23];
    const float* ln2w   = (const float*)d_in[24];
    const float* ln2b   = (const float*)d_in[25];
    const float* gamma2 = (const float*)d_in[26];
    const float* beta2  = (const float*)d_in[27];
    const float* vs2w   = (const float*)d_in[28];
    const float* vs2b   = (const float*)d_in[29];
    float* out = (float*)d_out;

    __half *Qh, *Kh, *Vh, *ctx, *h, *g1;
    float *xr, *x1, *f, *g;
    __half *WqT, *WkT, *WvT, *WoT, *fw1T, *fw2T, *gw1T, *gw2T;
    cudaGetSymbolAddress((void**)&Qh,   g_Qh);
    cudaGetSymbolAddress((void**)&Kh,   g_Kh);
    cudaGetSymbolAddress((void**)&Vh,   g_Vh);
    cudaGetSymbolAddress((void**)&ctx,  g_ctx);
    cudaGetSymbolAddress((void**)&xr,   g_xr);
    cudaGetSymbolAddress((void**)&x1,   g_x1);
    cudaGetSymbolAddress((void**)&h,    g_h);
    cudaGetSymbolAddress((void**)&f,    g_f);
    cudaGetSymbolAddress((void**)&g1,   g_g1);
    cudaGetSymbolAddress((void**)&g,    g_g);
    cudaGetSymbolAddress((void**)&WqT,  g_WqT);
    cudaGetSymbolAddress((void**)&WkT,  g_WkT);
    cudaGetSymbolAddress((void**)&WvT,  g_WvT);
    cudaGetSymbolAddress((void**)&WoT,  g_WoT);
    cudaGetSymbolAddress((void**)&fw1T, g_fw1T);
    cudaGetSymbolAddress((void**)&fw2T, g_fw2T);
    cudaGetSymbolAddress((void**)&gw1T, g_gw1T);
    cudaGetSymbolAddress((void**)&gw2T, g_gw2T);

    cudaFuncSetAttribute((const void*)mma_gemm<128, float, __half>,  cudaFuncAttributeMaxDynamicSharedMemorySize, SMEM_G128);
    cudaFuncSetAttribute((const void*)mma_gemm<128, float, float>,   cudaFuncAttributeMaxDynamicSharedMemorySize, SMEM_G128);
    cudaFuncSetAttribute((const void*)mma_gemm<128, __half, float>,  cudaFuncAttributeMaxDynamicSharedMemorySize, SMEM_G128);
    cudaFuncSetAttribute((const void*)mma_gemm<128, __half, __half>, cudaFuncAttributeMaxDynamicSharedMemorySize, SMEM_G128);

    // ---- weight transposes to fp16 ----
    transpose_h_kernel<<<dim3(Hsz/32, Hsz/32), 256>>>(Wq, Hsz, WqT, Hsz);
    transpose_h_kernel<<<dim3(Hsz/32, Hsz/32), 256>>>(Wk, Hsz, WkT, Hsz);
    transpose_h_kernel<<<dim3(Hsz/32, Hsz/32), 256>>>(Wv, Hsz, WvT, Hsz);
    transpose_h_kernel<<<dim3(Hsz/32, Hsz/32), 256>>>(Wo, Hsz, WoT, Hsz);
    transpose_h_kernel<<<dim3(HF/32,  Hsz/32), 256>>>(fw1, HF, fw1T, Hsz);
    transpose_h_kernel<<<dim3(Hsz/32, HF/32 ), 256>>>(fw2, Hsz, fw2T, HF);
    transpose_h_kernel<<<dim3(HG/32,  Hsz/32), 256>>>(gw1, HG, gw1T, Hsz);
    transpose_h_kernel<<<dim3(Hsz/32, HG/32 ), 256>>>(gw2, Hsz, gw2T, HG);

    // ---- QKV projections (Q pre-scaled by 1/8) ----
    mma_gemm<128, float, __half><<<dim3(8,64),256,SMEM_G128>>>(x,Hsz, WqT,Hsz, Qh,Hsz, bq,nullptr, Hsz, 0.125f,0);
    mma_gemm<128, float, __half><<<dim3(8,64),256,SMEM_G128>>>(x,Hsz, WkT,Hsz, Kh,Hsz, bk,nullptr, Hsz, 1.f,0);
    mma_gemm<128, float, __half><<<dim3(8,64),256,SMEM_G128>>>(x,Hsz, WvT,Hsz, Vh,Hsz, bv,nullptr, Hsz, 1.f,0);

    // ---- fused attention ----
    flash_attn<<<dim3(8, Bsz*NH), 256>>>(Qh, Kh, Vh, ctx);

    // ---- O projection + residual ----
    mma_gemm<128, __half, float><<<dim3(8,64),256,SMEM_G128>>>(ctx,Hsz, WoT,Hsz, xr,Hsz, bo,x, Hsz, 1.f,0);

    // ---- adaLN1 ----
    ada_ln_kernel<<<Mrows,256>>>(xr, vol, ln1w, ln1b, gamma1, beta1, vs1w, vs1b, x1);

    // ---- FFN ----
    mma_gemm<128, float, __half><<<dim3(32,64),256,SMEM_G128>>>(x1,Hsz, fw1T,Hsz, h,HF,  fb1,nullptr, Hsz, 1.f,1);
    mma_gemm<128, __half, float><<<dim3(8,64), 256,SMEM_G128>>>(h,HF,  fw2T,HF,  f,Hsz,  fb2,nullptr, HF,  1.f,0);

    // ---- gate ----
    mma_gemm<128, float, __half><<<dim3(4,64),256,SMEM_G128>>>(x1,Hsz, gw1T,Hsz, g1,HG, gb1,nullptr, Hsz, 1.f,2);
    mma_gemm<128, __half, float><<<dim3(8,64),256,SMEM_G128>>>(g1,HG,  gw2T,HG,  g,Hsz, gb2,nullptr, HG,  1.f,3);

    // ---- combine + adaLN2 -> out ----
    combine_ada_ln_kernel<<<Mrows,256>>>(x1, f, g, vol, ln2w, ln2b, gamma2, beta2, vs2w, vs2b, out);
}

// round 7
// speedup vs baseline: 8.9517x; 2.2945x over previous
#include <cuda_runtime.h>
#include <cuda_bf16.h>
#include <cuda_fp16.h>
#include <math.h>
#include <stdint.h>

// ---------------------------------------------------------------------------
// EnhancedTransformerBlock  B=8 S=1024 H=1024 nh=16 hd=64
// all-fp16 mma.sync GEMMs (cp.async + ldmatrix) + fused flash-attn
// ---------------------------------------------------------------------------

#define Bsz   8
#define Ssz   1024
#define Hsz   1024
#define NH    16
#define HD    64
#define Mrows (Bsz*Ssz)          // 8192
#define HF    (4*Hsz)            // 4096
#define HG    (Hsz/2)            // 512

// ------------------------- scratch (device globals) ------------------------
__device__ __half g_xh [(size_t)Mrows*Hsz];
__device__ __half g_Qh [(size_t)Mrows*Hsz];
__device__ __half g_Kh [(size_t)Mrows*Hsz];
__device__ __half g_Vh [(size_t)Mrows*Hsz];
__device__ __half g_ctx[(size_t)Mrows*Hsz];
__device__ float  g_xr [(size_t)Mrows*Hsz];
__device__ float  g_x1 [(size_t)Mrows*Hsz];
__device__ __half g_x1h[(size_t)Mrows*Hsz];
__device__ __half g_h  [(size_t)Mrows*HF];
__device__ float  g_f  [(size_t)Mrows*Hsz];
__device__ __half g_g1 [(size_t)Mrows*HG];
__device__ float  g_g  [(size_t)Mrows*Hsz];
// transposed fp16 weights ([N][K] K-major)
__device__ __half g_WqT [(size_t)Hsz*Hsz];
__device__ __half g_WkT [(size_t)Hsz*Hsz];
__device__ __half g_WvT [(size_t)Hsz*Hsz];
__device__ __half g_WoT [(size_t)Hsz*Hsz];
__device__ __half g_fw1T[(size_t)Hsz*HF];
__device__ __half g_fw2T[(size_t)HF*Hsz];
__device__ __half g_gw1T[(size_t)Hsz*HG];
__device__ __half g_gw2T[(size_t)HG*Hsz];

// ------------------------------ helpers ------------------------------------
__device__ __forceinline__ uint32_t pack_h2(float lo, float hi) {
    __half2 h = __floats2half2_rn(lo, hi);
    return *(uint32_t*)&h;
}
__device__ __forceinline__ void mma_f16(float* c, const uint32_t* a, const uint32_t* b) {
    asm volatile(
        "mma.sync.aligned.m16n8k16.row.col.f32.f16.f16.f32 "
        "{%0,%1,%2,%3}, {%4,%5,%6,%7}, {%8,%9}, {%0,%1,%2,%3};"
        : "+f"(c[0]), "+f"(c[1]), "+f"(c[2]), "+f"(c[3])
        : "r"(a[0]), "r"(a[1]), "r"(a[2]), "r"(a[3]), "r"(b[0]), "r"(b[1]));
}
__device__ __forceinline__ int sw128(int byte) {
    return byte ^ ((byte >> 3) & 0x70);
}
__device__ __forceinline__ uint32_t smem_addr(const void* p) {
    return (uint32_t)__cvta_generic_to_shared(p);
}
__device__ __forceinline__ void cp16(uint32_t dst, const void* src) {
    asm volatile("cp.async.cg.shared.global [%0], [%1], 16;" :: "r"(dst), "l"(src));
}
__device__ __forceinline__ void cp_commit() { asm volatile("cp.async.commit_group;" ::: "memory"); }
template<int N> __device__ __forceinline__ void cp_wait() {
    asm volatile("cp.async.wait_group %0;" :: "n"(N) : "memory");
}
__device__ __forceinline__ void ldmx4(uint32_t* r, uint32_t addr) {
    asm volatile("ldmatrix.sync.aligned.m8n8.x4.shared.b16 {%0,%1,%2,%3}, [%4];"
        : "=r"(r[0]), "=r"(r[1]), "=r"(r[2]), "=r"(r[3]) : "r"(addr));
}

// ----------------------------- FP16 GEMM -----------------------------------
// C[m,n] = act((sum_k A[m,k]*B[n,k] + bias[n]) * alpha) (+resid)
// A fp16 [M,K] K-major, B fp16 [N,K] K-major; tile 128x128, k-chunk 64.
template<typename CT>
__global__ __launch_bounds__(256)
void mma_gemm(const __half* __restrict__ A, int lda,
              const __half* __restrict__ B, int ldb,
              CT* __restrict__ C, int ldc,
              const float* __restrict__ bias, const float* __restrict__ resid,
              int K, float alpha, int act)
{
    extern __shared__ char sm[];
    char* Ab[2] = { sm,         sm + 32768 };
    char* Bb[2] = { sm + 16384, sm + 49152 };

    const int tid = threadIdx.x, wid = tid >> 5, lane = tid & 31;
    const int gid = lane >> 2, tig = lane & 3;
    const int warpm = wid & 1, warpn = wid >> 1;

    const int m0 = blockIdx.y * 128;
    const int n0 = blockIdx.x * 128;

    float c[4][4][4];
    #pragma unroll
    for (int mi = 0; mi < 4; mi++)
        #pragma unroll
        for (int ni = 0; ni < 4; ni++)
            #pragma unroll
            for (int e = 0; e < 4; e++) c[mi][ni][e] = 0.f;

    const int sr = tid >> 3, scq = tid & 7;     // staging: row base 0..31, 16B col 0..7

    auto stage = [&](int kt, int buf) {
        #pragma unroll
        for (int i = 0; i < 4; i++) {           // rows sr, sr+32, sr+64, sr+96
            const int r = sr + i * 32;
            const int swb = sw128(r * 128 + scq * 16);
            cp16(smem_addr(Ab[buf] + swb), A + (size_t)(m0 + r) * lda + kt + scq * 8);
            cp16(smem_addr(Bb[buf] + swb), B + (size_t)(n0 + r) * ldb + kt + scq * 8);
        }
    };

    stage(0, 0);
    cp_commit();

    const int nch = K >> 6;
    for (int ch = 0; ch < nch; ch++) {
        const int buf = ch & 1;
        if (ch + 1 < nch) { stage((ch + 1) << 6, buf ^ 1); cp_commit(); cp_wait<1>(); }
        else              { cp_wait<0>(); }
        __syncthreads();

        const char* As = Ab[buf];
        const char* Bs = Bb[buf];
        #pragma unroll
        for (int ks = 0; ks < 4; ks++) {
            uint32_t a[4][4], b[4][2];
            #pragma unroll
            for (int mi = 0; mi < 4; mi++) {
                int row = warpm * 64 + mi * 16 + (lane & 15);
                int colb = ks * 32 + ((lane & 16) ? 16 : 0);
                ldmx4(a[mi], smem_addr(As + sw128(row * 128 + colb)));
            }
            #pragma unroll
            for (int np = 0; np < 2; np++) {
                int row = warpn * 32 + np * 16 + (lane & 7) + ((lane & 16) ? 8 : 0);
                int colb = ks * 32 + ((lane & 8) ? 16 : 0);
                uint32_t t[4];
                ldmx4(t, smem_addr(Bs + sw128(row * 128 + colb)));
                b[2*np][0] = t[0]; b[2*np][1] = t[1];
                b[2*np+1][0] = t[2]; b[2*np+1][1] = t[3];
            }
            #pragma unroll
            for (int mi = 0; mi < 4; mi++)
                #pragma unroll
                for (int ni = 0; ni < 4; ni++)
                    mma_f16(c[mi][ni], a[mi], b[ni]);
        }
        __syncthreads();
    }

    // ------------------------------ epilogue --------------------------------
    #pragma unroll
    for (int mi = 0; mi < 4; mi++) {
        #pragma unroll
        for (int ni = 0; ni < 4; ni++) {
            const int col = n0 + warpn * 32 + ni * 8 + 2 * tig;
            float bx = 0.f, by = 0.f;
            if (bias) { bx = bias[col]; by = bias[col + 1]; }
            #pragma unroll
            for (int h = 0; h < 2; h++) {
                const int row = m0 + warpm * 64 + mi * 16 + gid + h * 8;
                float v0 = (c[mi][ni][2*h + 0] + bx) * alpha;
                float v1 = (c[mi][ni][2*h + 1] + by) * alpha;
                if (act == 1) {
                    v0 = 0.5f * v0 * (1.0f + erff(v0 * 0.70710678118654752f));
                    v1 = 0.5f * v1 * (1.0f + erff(v1 * 0.70710678118654752f));
                } else if (act == 2) {
                    v0 = fmaxf(v0, 0.f); v1 = fmaxf(v1, 0.f);
                } else if (act == 3) {
                    v0 = 1.f / (1.f + expf(-v0)); v1 = 1.f / (1.f + expf(-v1));
                }
                const long long g = (long long)row * ldc + col;
                if (sizeof(CT) == 2) {
                    *(__half2*)((__half*)C + g) = __floats2half2_rn(v0, v1);
                } else {
                    if (resid) {
                        float2 q = *(const float2*)(resid + g);
                        v0 += q.x; v1 += q.y;
                    }
                    float2 o; o.x = v0; o.y = v1;
                    *(float2*)((float*)C + g) = o;
                }
            }
        }
    }
}

// ----------------------- fused flash attention ------------------------------
// ctx[b, q, h*64+d] = softmax(Q K^T) V   (scale pre-folded into Q)
__global__ __launch_bounds__(256)
void flash_attn(const __half* __restrict__ Qh, const __half* __restrict__ Kh,
                const __half* __restrict__ Vh, __half* __restrict__ ctx)
{
    extern __shared__ char sm[];
    char* Qs = sm;                       // 16 KB
    char* Kb[2] = { sm + 16384, sm + 32768 };
    char* Vb[2] = { sm + 24576, sm + 40960 };

    const int tid = threadIdx.x, wid = tid >> 5, lane = tid & 31;
    const int gid = lane >> 2, tig = lane & 3;
    const int qt = blockIdx.x, bh = blockIdx.y;
    const int b = bh >> 4, hh = bh & 15;

    const __half* Qg = Qh + ((size_t)(b * 1024 + qt * 128) * 1024 + hh * 64);
    const __half* Kg = Kh + ((size_t)b * 1024 * 1024 + hh * 64);
    const __half* Vg = Vh + ((size_t)b * 1024 * 1024 + hh * 64);

    // stage Q (128 x 64 half = 128B/row, SW128) via cp.async
    #pragma unroll
    for (int i = 0; i < 4; i++) {
        int id = tid + i * 256;
        int r = id >> 3, cc = id & 7;
        cp16(smem_addr(Qs + sw128(r * 128 + cc * 16)), Qg + (size_t)r * 1024 + cc * 8);
    }
    cp_commit();

    auto stage_kv = [&](int kt, int buf) {
        #pragma unroll
        for (int i = 0; i < 2; i++) {
            int id = tid + i * 256;
            int r = id >> 3, cc = id & 7;
            int swb = sw128(r * 128 + cc * 16);
            cp16(smem_addr(Kb[buf] + swb), Kg + (size_t)(kt * 64 + r) * 1024 + cc * 8);
            cp16(smem_addr(Vb[buf] + swb), Vg + (size_t)(kt * 64 + r) * 1024 + cc * 8);
        }
    };
    stage_kv(0, 0);
    cp_commit();

    cp_wait<1>();          // Q group done
    __syncthreads();

    uint32_t qf[4][4];
    #pragma unroll
    for (int ks = 0; ks < 4; ks++) {
        int row = wid * 16 + (lane & 15);
        int colb = ks * 32 + ((lane & 16) ? 16 : 0);
        ldmx4(qf[ks], smem_addr(Qs + sw128(row * 128 + colb)));
    }

    float m0 = -1e30f, m1 = -1e30f, l0 = 0.f, l1 = 0.f;
    float o[8][4];
    #pragma unroll
    for (int nt = 0; nt < 8; nt++)
        #pragma unroll
        for (int e = 0; e < 4; e++) o[nt][e] = 0.f;

    for (int kt = 0; kt < 16; kt++) {
        const int buf = kt & 1;
        if (kt + 1 < 16) { stage_kv(kt + 1, buf ^ 1); cp_commit(); cp_wait<1>(); }
        else             { cp_wait<0>(); }
        __syncthreads();

        // ---- S = Q @ K^T ----
        float s[8][4];
        #pragma unroll
        for (int nt = 0; nt < 8; nt++)
            #pragma unroll
            for (int e = 0; e < 4; e++) s[nt][e] = 0.f;

        #pragma unroll
        for (int ks = 0; ks < 4; ks++) {
            uint32_t kb[8][2];
            #pragma unroll
            for (int ntp = 0; ntp < 4; ntp++) {
                int row = ntp * 16 + (lane & 7) + ((lane & 16) ? 8 : 0);
                int colb = ks * 32 + ((lane & 8) ? 16 : 0);
                uint32_t t[4];
                ldmx4(t, smem_addr(Kb[buf] + sw128(row * 128 + colb)));
                kb[2*ntp][0] = t[0]; kb[2*ntp][1] = t[1];
                kb[2*ntp+1][0] = t[2]; kb[2*ntp+1][1] = t[3];
            }
            #pragma unroll
            for (int nt = 0; nt < 8; nt++)
                mma_f16(s[nt], qf[ks], kb[nt]);
        }

        // ---- online softmax ----
        float mc0 = -1e30f, mc1 = -1e30f;
        #pragma unroll
        for (int nt = 0; nt < 8; nt++) {
            mc0 = fmaxf(mc0, fmaxf(s[nt][0], s[nt][1]));
            mc1 = fmaxf(mc1, fmaxf(s[nt][2], s[nt][3]));
        }
        mc0 = fmaxf(mc0, __shfl_xor_sync(0xffffffffu, mc0, 1));
        mc0 = fmaxf(mc0, __shfl_xor_sync(0xffffffffu, mc0, 2));
        mc1 = fmaxf(mc1, __shfl_xor_sync(0xffffffffu, mc1, 1));
        mc1 = fmaxf(mc1, __shfl_xor_sync(0xffffffffu, mc1, 2));
        float mn0 = fmaxf(m0, mc0), mn1 = fmaxf(m1, mc1);
        float sc0 = __expf(m0 - mn0), sc1 = __expf(m1 - mn1);
        m0 = mn0; m1 = mn1;

        float rs0 = 0.f, rs1 = 0.f;
        uint32_t pf[8][2];
        #pragma unroll
        for (int nt = 0; nt < 8; nt++) {
            float p0 = __expf(s[nt][0] - mn0);
            float p1 = __expf(s[nt][1] - mn0);
            float p2 = __expf(s[nt][2] - mn1);
            float p3 = __expf(s[nt][3] - mn1);
            rs0 += p0 + p1; rs1 += p2 + p3;
            pf[nt][0] = pack_h2(p0, p1);
            pf[nt][1] = pack_h2(p2, p3);
        }
        rs0 += __shfl_xor_sync(0xffffffffu, rs0, 1);
        rs0 += __shfl_xor_sync(0xffffffffu, rs0, 2);
        rs1 += __shfl_xor_sync(0xffffffffu, rs1, 1);
        rs1 += __shfl_xor_sync(0xffffffffu, rs1, 2);
        l0 = l0 * sc0 + rs0;
        l1 = l1 * sc1 + rs1;
        #pragma unroll
        for (int nt = 0; nt < 8; nt++) {
            o[nt][0] *= sc0; o[nt][1] *= sc0;
            o[nt][2] *= sc1; o[nt][3] *= sc1;
        }

        // ---- O += P @ V ----
        #pragma unroll
        for (int ks = 0; ks < 4; ks++) {
            uint32_t vb[8][2];
            #pragma unroll
            for (int ntp = 0; ntp < 4; ntp++) {
                int row = ks * 16 + (lane & 7) + ((lane & 8) ? 8 : 0);
                int colb = ntp * 32 + ((lane & 16) ? 16 : 0);
                uint32_t t[4];
                asm volatile("ldmatrix.sync.aligned.m8n8.x4.trans.shared.b16 {%0,%1,%2,%3}, [%4];"
                    : "=r"(t[0]), "=r"(t[1]), "=r"(t[2]), "=r"(t[3])
                    : "r"(smem_addr(Vb[buf] + sw128(row * 128 + colb))));
                vb[2*ntp][0] = t[0]; vb[2*ntp][1] = t[1];
                vb[2*ntp+1][0] = t[2]; vb[2*ntp+1][1] = t[3];
            }
            uint32_t a[4] = { pf[2*ks][0], pf[2*ks][1], pf[2*ks+1][0], pf[2*ks+1][1] };
            #pragma unroll
            for (int nt = 0; nt < 8; nt++)
                mma_f16(o[nt], a, vb[nt]);
        }
        __syncthreads();
    }

    // ---- epilogue ----
    float inv0 = 1.f / l0, inv1 = 1.f / l1;
    const int row0 = b * 1024 + qt * 128 + wid * 16 + gid;
    #pragma unroll
    for (int nt = 0; nt < 8; nt++) {
        int col = hh * 64 + nt * 8 + 2 * tig;
        *(__half2*)(ctx + (size_t)row0 * 1024 + col) =
            __floats2half2_rn(o[nt][0] * inv0, o[nt][1] * inv0);
        *(__half2*)(ctx + (size_t)(row0 + 8) * 1024 + col) =
            __floats2half2_rn(o[nt][2] * inv1, o[nt][3] * inv1);
    }
}

// ------------------- weight transpose (fp32 -> fp16) ------------------------
__global__ __launch_bounds__(256)
void transpose_h_kernel(const float* __restrict__ in, int ldi,
                        __half* __restrict__ out, int ldo)
{
    __shared__ float t[32][33];
    const int r0 = blockIdx.y * 32, c0 = blockIdx.x * 32;
    const int tx = threadIdx.x & 31, ty = threadIdx.x >> 5;
    #pragma unroll
    for (int i = 0; i < 32; i += 8)
        t[ty + i][tx] = in[(long long)(r0 + ty + i) * ldi + c0 + tx];
    __syncthreads();
    #pragma unroll
    for (int i = 0; i < 32; i += 8)
        out[(long long)(c0 + ty + i) * ldo + r0 + tx] = __float2half(t[tx][ty + i]);
}

// --------------------------- fp32 -> fp16 copy ------------------------------
__global__ __launch_bounds__(256)
void f2h_kernel(const float* __restrict__ in, __half* __restrict__ out)
{
    const long long i = ((long long)blockIdx.x * 256 + threadIdx.x) * 4;
    float4 v = *(const float4*)(in + i);
    __half2 a = __floats2half2_rn(v.x, v.y);
    __half2 b = __floats2half2_rn(v.z, v.w);
    *(uint2*)(out + i) = make_uint2(*(uint32_t*)&a, *(uint32_t*)&b);
}

// -------------------------- block reduce (256 thr) --------------------------
__device__ __forceinline__ float blk_sum256(float v)
{
    __shared__ float sm[8];
    const int lane = threadIdx.x & 31, w = threadIdx.x >> 5;
    #pragma unroll
    for (int o = 16; o; o >>= 1) v += __shfl_xor_sync(0xffffffffu, v, o);
    if (lane == 0) sm[w] = v;
    __syncthreads();
    if (w == 0) {
        float r = (lane < 8) ? sm[lane] : 0.f;
        #pragma unroll
        for (int o = 4; o; o >>= 1) r += __shfl_xor_sync(0xffffffffu, r, o);
        if (lane == 0) sm[0] = r;
    }
    __syncthreads();
    float r = sm[0];
    __syncthreads();
    return r;
}

// ------------------------------- adaLN --------------------------------------
// writes fp32 out and fp16 outh
__global__ __launch_bounds__(256)
void ada_ln_kernel(const float* __restrict__ in, const float* __restrict__ vol,
                   const float* __restrict__ w, const float* __restrict__ b,
                   const float* __restrict__ gamma, const float* __restrict__ beta,
                   const float* __restrict__ vsw, const float* __restrict__ vsb,
                   float* __restrict__ out, __half* __restrict__ outh)
{
    const long long row = blockIdx.x;
    const int t = threadIdx.x;
    float4 v = *(const float4*)(in + row * 1024 + t * 4);

    float mu = blk_sum256(v.x + v.y + v.z + v.w) * (1.f / 1024.f);
    float dx = v.x - mu, dy = v.y - mu, dz = v.z - mu, dw = v.w - mu;
    float var = blk_sum256(dx * dx + dy * dy + dz * dz + dw * dw) * (1.f / 1024.f);
    float inv = rsqrtf(var + 1e-5f);

    float vs = 1.f / (1.f + expf(-(vol[row] * (*vsw) + (*vsb))));
    float k1 = (1.f + vs) * (*gamma);
    float k0 = *beta;

    float4 w4 = *(const float4*)(w + t * 4);
    float4 b4 = *(const float4*)(b + t * 4);
    float4 o;
    o.x = (dx * inv * w4.x + b4.x) * k1 + k0;
    o.y = (dy * inv * w4.y + b4.y) * k1 + k0;
    o.z = (dz * inv * w4.z + b4.z) * k1 + k0;
    o.w = (dw * inv * w4.w + b4.w) * k1 + k0;
    *(float4*)(out + row * 1024 + t * 4) = o;
    __half2 ha = __floats2half2_rn(o.x, o.y);
    __half2 hb = __floats2half2_rn(o.z, o.w);
    *(uint2*)(outh + row * 1024 + t * 4) = make_uint2(*(uint32_t*)&ha, *(uint32_t*)&hb);
}

// -------- combine (x1*(2-g) + ffn*g) then adaLN2 -> out ----------------------
__global__ __launch_bounds__(256)
void combine_ada_ln_kernel(const float* __restrict__ x1, const float* __restrict__ f,
                           const float* __restrict__ g,  const float* __restrict__ vol,
                           const float* __restrict__ w,  const float* __restrict__ b,
                           const float* __restrict__ gamma, const float* __restrict__ beta,
                           const float* __restrict__ vsw, const float* __restrict__ vsb,
                           float* __restrict__ out)
{
    const long long row = blockIdx.x;
    const int t = threadIdx.x;
    float4 a  = *(const float4*)(x1 + row * 1024 + t * 4);
    float4 ff = *(const float4*)(f  + row * 1024 + t * 4);
    float4 gg = *(const float4*)(g  + row * 1024 + t * 4);

    float4 v;
    v.x = a.x * (2.f - gg.x) + ff.x * gg.x;
    v.y = a.y * (2.f - gg.y) + ff.y * gg.y;
    v.z = a.z * (2.f - gg.z) + ff.z * gg.z;
    v.w = a.w * (2.f - gg.w) + ff.w * gg.w;

    float mu = blk_sum256(v.x + v.y + v.z + v.w) * (1.f / 1024.f);
    float dx = v.x - mu, dy = v.y - mu, dz = v.z - mu, dw = v.w - mu;
    float var = blk_sum256(dx * dx + dy * dy + dz * dz + dw * dw) * (1.f / 1024.f);
    float inv = rsqrtf(var + 1e-5f);

    float vs = 1.f / (1.f + expf(-(vol[row] * (*vsw) + (*vsb))));
    float k1 = (1.f + vs) * (*gamma);
    float k0 = *beta;

    float4 w4 = *(const float4*)(w + t * 4);
    float4 b4 = *(const float4*)(b + t * 4);
    float4 o;
    o.x = (dx * inv * w4.x + b4.x) * k1 + k0;
    o.y = (dy * inv * w4.y + b4.y) * k1 + k0;
    o.z = (dz * inv * w4.z + b4.z) * k1 + k0;
    o.w = (dw * inv * w4.w + b4.w) * k1 + k0;
    *(float4*)(out + row * 1024 + t * 4) = o;
}

// ------------------------------ launcher ------------------------------------
#define SMEM_GEMM  65536
#define SMEM_FLASH 49152

extern "C" void kernel_launch(void* const* d_in, const int* in_sizes, int n_in,
                              void* d_out, int out_size)
{
    const float* x      = (const float*)d_in[0];
    const float* vol    = (const float*)d_in[1];
    const float* Wq     = (const float*)d_in[2];
    const float* bq     = (const float*)d_in[3];
    const float* Wk     = (const float*)d_in[4];
    const float* bk     = (const float*)d_in[5];
    const float* Wv     = (const float*)d_in[6];
    const float* bv     = (const float*)d_in[7];
    const float* Wo     = (const float*)d_in[8];
    const float* bo     = (const float*)d_in[9];
    const float* ln1w   = (const float*)d_in[10];
    const float* ln1b   = (const float*)d_in[11];
    const float* gamma1 = (const float*)d_in[12];
    const float* beta1  = (const float*)d_in[13];
    const float* vs1w   = (const float*)d_in[14];
    const float* vs1b   = (const float*)d_in[15];
    const float* fw1    = (const float*)d_in[16];
    const float* fb1    = (const float*)d_in[17];
    const float* fw2    = (const float*)d_in[18];
    const float* fb2    = (const float*)d_in[19];
    const float* gw1    = (const float*)d_in[20];
    const float* gb1    = (const float*)d_in[21];
    const float* gw2    = (const float*)d_in[22];
    const float* gb2    = (const float*)d_in[23];
    const float* ln2w   = (const float*)d_in[24];
    const float* ln2b   = (const float*)d_in[25];
    const float* gamma2 = (const float*)d_in[26];
    const float* beta2  = (const float*)d_in[27];
    const float* vs2w   = (const float*)d_in[28];
    const float* vs2b   = (const float*)d_in[29];
    float* out = (float*)d_out;

    __half *xh, *Qh, *Kh, *Vh, *ctx, *h, *g1, *x1h;
    float *xr, *x1, *f, *g;
    __half *WqT, *WkT, *WvT, *WoT, *fw1T, *fw2T, *gw1T, *gw2T;
    cudaGetSymbolAddress((void**)&xh,   g_xh);
    cudaGetSymbolAddress((void**)&Qh,   g_Qh);
    cudaGetSymbolAddress((void**)&Kh,   g_Kh);
    cudaGetSymbolAddress((void**)&Vh,   g_Vh);
    cudaGetSymbolAddress((void**)&ctx,  g_ctx);
    cudaGetSymbolAddress((void**)&xr,   g_xr);
    cudaGetSymbolAddress((void**)&x1,   g_x1);
    cudaGetSymbolAddress((void**)&x1h,  g_x1h);
    cudaGetSymbolAddress((void**)&h,    g_h);
    cudaGetSymbolAddress((void**)&f,    g_f);
    cudaGetSymbolAddress((void**)&g1,   g_g1);
    cudaGetSymbolAddress((void**)&g,    g_g);
    cudaGetSymbolAddress((void**)&WqT,  g_WqT);
    cudaGetSymbolAddress((void**)&WkT,  g_WkT);
    cudaGetSymbolAddress((void**)&WvT,  g_WvT);
    cudaGetSymbolAddress((void**)&WoT,  g_WoT);
    cudaGetSymbolAddress((void**)&fw1T, g_fw1T);
    cudaGetSymbolAddress((void**)&fw2T, g_fw2T);
    cudaGetSymbolAddress((void**)&gw1T, g_gw1T);
    cudaGetSymbolAddress((void**)&gw2T, g_gw2T);

    cudaFuncSetAttribute((const void*)mma_gemm<__half>, cudaFuncAttributeMaxDynamicSharedMemorySize, SMEM_GEMM);
    cudaFuncSetAttribute((const void*)mma_gemm<float>,  cudaFuncAttributeMaxDynamicSharedMemorySize, SMEM_GEMM);
    cudaFuncSetAttribute((const void*)flash_attn,       cudaFuncAttributeMaxDynamicSharedMemorySize, SMEM_FLASH);

    // ---- weight transposes to fp16 + x conversion ----
    transpose_h_kernel<<<dim3(Hsz/32, Hsz/32), 256>>>(Wq, Hsz, WqT, Hsz);
    transpose_h_kernel<<<dim3(Hsz/32, Hsz/32), 256>>>(Wk, Hsz, WkT, Hsz);
    transpose_h_kernel<<<dim3(Hsz/32, Hsz/32), 256>>>(Wv, Hsz, WvT, Hsz);
    transpose_h_kernel<<<dim3(Hsz/32, Hsz/32), 256>>>(Wo, Hsz, WoT, Hsz);
    transpose_h_kernel<<<dim3(HF/32,  Hsz/32), 256>>>(fw1, HF, fw1T, Hsz);
    transpose_h_kernel<<<dim3(Hsz/32, HF/32 ), 256>>>(fw2, Hsz, fw2T, HF);
    transpose_h_kernel<<<dim3(HG/32,  Hsz/32), 256>>>(gw1, HG, gw1T, Hsz);
    transpose_h_kernel<<<dim3(Hsz/32, HG/32 ), 256>>>(gw2, Hsz, gw2T, HG);
    f2h_kernel<<<(size_t)Mrows*Hsz/1024, 256>>>(x, xh);

    // ---- QKV projections (Q pre-scaled by 1/8) ----
    mma_gemm<__half><<<dim3(8,64),256,SMEM_GEMM>>>(xh,Hsz, WqT,Hsz, Qh,Hsz, bq,nullptr, Hsz, 0.125f,0);
    mma_gemm<__half><<<dim3(8,64),256,SMEM_GEMM>>>(xh,Hsz, WkT,Hsz, Kh,Hsz, bk,nullptr, Hsz, 1.f,0);
    mma_gemm<__half><<<dim3(8,64),256,SMEM_GEMM>>>(xh,Hsz, WvT,Hsz, Vh,Hsz, bv,nullptr, Hsz, 1.f,0);

    // ---- fused attention ----
    flash_attn<<<dim3(8, Bsz*NH), 256, SMEM_FLASH>>>(Qh, Kh, Vh, ctx);

    // ---- O projection + residual ----
    mma_gemm<float><<<dim3(8,64),256,SMEM_GEMM>>>(ctx,Hsz, WoT,Hsz, xr,Hsz, bo,x, Hsz, 1.f,0);

    // ---- adaLN1 (fp32 + fp16 outputs) ----
    ada_ln_kernel<<<Mrows,256>>>(xr, vol, ln1w, ln1b, gamma1, beta1, vs1w, vs1b, x1, x1h);

    // ---- FFN ----
    mma_gemm<__half><<<dim3(32,64),256,SMEM_GEMM>>>(x1h,Hsz, fw1T,Hsz, h,HF,  fb1,nullptr, Hsz, 1.f,1);
    mma_gemm<float> <<<dim3(8,64), 256,SMEM_GEMM>>>(h,HF,   fw2T,HF,  f,Hsz, fb2,nullptr, HF,  1.f,0);

    // ---- gate ----
    mma_gemm<__half><<<dim3(4,64),256,SMEM_GEMM>>>(x1h,Hsz, gw1T,Hsz, g1,HG, gb1,nullptr, Hsz, 1.f,2);
    mma_gemm<float> <<<dim3(8,64),256,SMEM_GEMM>>>(g1,HG,   gw2T,HG,  g,Hsz, gb2,nullptr, HG,  1.f,3);

    // ---- combine + adaLN2 -> out ----
    combine_ada_ln_kernel<<<Mrows,256>>>(x1, f, g, vol, ln2w, ln2b, gamma2, beta2, vs2w, vs2b, out);
}

// round 8
// speedup vs baseline: 9.0282x; 1.0086x over previous
#include <cuda_runtime.h>
#include <cuda_bf16.h>
#include <cuda_fp16.h>
#include <math.h>
#include <stdint.h>

// ---------------------------------------------------------------------------
// EnhancedTransformerBlock  B=8 S=1024 H=1024 nh=16 hd=64
// all-fp16 mma.sync GEMMs (cp.async + ldmatrix, 2 CTA/SM) + fused flash-attn
// ---------------------------------------------------------------------------

#define Bsz   8
#define Ssz   1024
#define Hsz   1024
#define NH    16
#define HD    64
#define Mrows (Bsz*Ssz)          // 8192
#define HF    (4*Hsz)            // 4096
#define HG    (Hsz/2)            // 512
#define H3    (3*Hsz)            // 3072

// ------------------------- scratch (device globals) ------------------------
__device__ __half g_xh  [(size_t)Mrows*Hsz];
__device__ __half g_QKV [(size_t)Mrows*H3];       // packed Q|K|V rows
__device__ __half g_ctx [(size_t)Mrows*Hsz];
__device__ float  g_xr  [(size_t)Mrows*Hsz];
__device__ float  g_x1  [(size_t)Mrows*Hsz];
__device__ __half g_x1h [(size_t)Mrows*Hsz];
__device__ __half g_h   [(size_t)Mrows*HF];
__device__ float  g_f   [(size_t)Mrows*Hsz];
__device__ __half g_g1  [(size_t)Mrows*HG];
__device__ float  g_g   [(size_t)Mrows*Hsz];
// transposed fp16 weights ([N][K] K-major)
__device__ __half g_WqkvT[(size_t)H3*Hsz];        // rows: [Wq*0.125 | Wk | Wv]
__device__ float  g_bqkv [H3];
__device__ __half g_WoT [(size_t)Hsz*Hsz];
__device__ __half g_fw1T[(size_t)Hsz*HF];
__device__ __half g_fw2T[(size_t)HF*Hsz];
__device__ __half g_gw1T[(size_t)Hsz*HG];
__device__ __half g_gw2T[(size_t)HG*Hsz];

// ------------------------------ helpers ------------------------------------
__device__ __forceinline__ uint32_t pack_h2(float lo, float hi) {
    __half2 h = __floats2half2_rn(lo, hi);
    return *(uint32_t*)&h;
}
__device__ __forceinline__ void mma_f16(float* c, const uint32_t* a, const uint32_t* b) {
    asm volatile(
        "mma.sync.aligned.m16n8k16.row.col.f32.f16.f16.f32 "
        "{%0,%1,%2,%3}, {%4,%5,%6,%7}, {%8,%9}, {%0,%1,%2,%3};"
        : "+f"(c[0]), "+f"(c[1]), "+f"(c[2]), "+f"(c[3])
        : "r"(a[0]), "r"(a[1]), "r"(a[2]), "r"(a[3]), "r"(b[0]), "r"(b[1]));
}
__device__ __forceinline__ int sw128(int byte) {
    return byte ^ ((byte >> 3) & 0x70);
}
__device__ __forceinline__ uint32_t smem_addr(const void* p) {
    return (uint32_t)__cvta_generic_to_shared(p);
}
__device__ __forceinline__ void cp16(uint32_t dst, const void* src) {
    asm volatile("cp.async.cg.shared.global [%0], [%1], 16;" :: "r"(dst), "l"(src));
}
__device__ __forceinline__ void cp_commit() { asm volatile("cp.async.commit_group;" ::: "memory"); }
template<int N> __device__ __forceinline__ void cp_wait() {
    asm volatile("cp.async.wait_group %0;" :: "n"(N) : "memory");
}
__device__ __forceinline__ void ldmx4(uint32_t* r, uint32_t addr) {
    asm volatile("ldmatrix.sync.aligned.m8n8.x4.shared.b16 {%0,%1,%2,%3}, [%4];"
        : "=r"(r[0]), "=r"(r[1]), "=r"(r[2]), "=r"(r[3]) : "r"(addr));
}

// ----------------------------- FP16 GEMM -----------------------------------
// C[m,n] = act(sum_k A[m,k]*B[n,k] + bias[n]) (+resid)
// A fp16 [M,K] K-major, B fp16 [N,K] K-major; tile 128x128, k-chunk 64.
template<typename CT>
__global__ __launch_bounds__(256, 2)
void mma_gemm(const __half* __restrict__ A, int lda,
              const __half* __restrict__ B, int ldb,
              CT* __restrict__ C, int ldc,
              const float* __restrict__ bias, const float* __restrict__ resid,
              int K, int act)
{
    extern __shared__ char sm[];
    char* Ab[2] = { sm,         sm + 32768 };
    char* Bb[2] = { sm + 16384, sm + 49152 };

    const int tid = threadIdx.x, wid = tid >> 5, lane = tid & 31;
    const int gid = lane >> 2, tig = lane & 3;
    const int warpm = wid & 1, warpn = wid >> 1;

    const int m0 = blockIdx.y * 128;
    const int n0 = blockIdx.x * 128;

    float c[4][4][4];
    #pragma unroll
    for (int mi = 0; mi < 4; mi++)
        #pragma unroll
        for (int ni = 0; ni < 4; ni++)
            #pragma unroll
            for (int e = 0; e < 4; e++) c[mi][ni][e] = 0.f;

    const int sr = tid >> 3, scq = tid & 7;     // staging: row base 0..31, 16B col 0..7

    auto stage = [&](int kt, int buf) {
        #pragma unroll
        for (int i = 0; i < 4; i++) {           // rows sr, sr+32, sr+64, sr+96
            const int r = sr + i * 32;
            const int swb = sw128(r * 128 + scq * 16);
            cp16(smem_addr(Ab[buf] + swb), A + (size_t)(m0 + r) * lda + kt + scq * 8);
            cp16(smem_addr(Bb[buf] + swb), B + (size_t)(n0 + r) * ldb + kt + scq * 8);
        }
    };

    stage(0, 0);
    cp_commit();

    const int nch = K >> 6;
    for (int ch = 0; ch < nch; ch++) {
        const int buf = ch & 1;
        if (ch + 1 < nch) { stage((ch + 1) << 6, buf ^ 1); cp_commit(); cp_wait<1>(); }
        else              { cp_wait<0>(); }
        __syncthreads();

        const char* As = Ab[buf];
        const char* Bs = Bb[buf];
        #pragma unroll
        for (int ks = 0; ks < 4; ks++) {
            uint32_t a[4][4], b[4][2];
            #pragma unroll
            for (int mi = 0; mi < 4; mi++) {
                int row = warpm * 64 + mi * 16 + (lane & 15);
                int colb = ks * 32 + ((lane & 16) ? 16 : 0);
                ldmx4(a[mi], smem_addr(As + sw128(row * 128 + colb)));
            }
            #pragma unroll
            for (int np = 0; np < 2; np++) {
                int row = warpn * 32 + np * 16 + (lane & 7) + ((lane & 16) ? 8 : 0);
                int colb = ks * 32 + ((lane & 8) ? 16 : 0);
                uint32_t t[4];
                ldmx4(t, smem_addr(Bs + sw128(row * 128 + colb)));
                b[2*np][0] = t[0]; b[2*np][1] = t[1];
                b[2*np+1][0] = t[2]; b[2*np+1][1] = t[3];
            }
            #pragma unroll
            for (int mi = 0; mi < 4; mi++)
                #pragma unroll
                for (int ni = 0; ni < 4; ni++)
                    mma_f16(c[mi][ni], a[mi], b[ni]);
        }
        __syncthreads();
    }

    // ------------------------------ epilogue --------------------------------
    #pragma unroll
    for (int mi = 0; mi < 4; mi++) {
        #pragma unroll
        for (int ni = 0; ni < 4; ni++) {
            const int col = n0 + warpn * 32 + ni * 8 + 2 * tig;
            float bx = 0.f, by = 0.f;
            if (bias) { bx = bias[col]; by = bias[col + 1]; }
            #pragma unroll
            for (int h = 0; h < 2; h++) {
                const int row = m0 + warpm * 64 + mi * 16 + gid + h * 8;
                float v0 = c[mi][ni][2*h + 0] + bx;
                float v1 = c[mi][ni][2*h + 1] + by;
                if (act == 1) {
                    v0 = 0.5f * v0 * (1.0f + erff(v0 * 0.70710678118654752f));
                    v1 = 0.5f * v1 * (1.0f + erff(v1 * 0.70710678118654752f));
                } else if (act == 2) {
                    v0 = fmaxf(v0, 0.f); v1 = fmaxf(v1, 0.f);
                } else if (act == 3) {
                    v0 = 1.f / (1.f + expf(-v0)); v1 = 1.f / (1.f + expf(-v1));
                }
                const long long g = (long long)row * ldc + col;
                if (sizeof(CT) == 2) {
                    *(__half2*)((__half*)C + g) = __floats2half2_rn(v0, v1);
                } else {
                    if (resid) {
                        float2 q = *(const float2*)(resid + g);
                        v0 += q.x; v1 += q.y;
                    }
                    float2 o; o.x = v0; o.y = v1;
                    *(float2*)((float*)C + g) = o;
                }
            }
        }
    }
}

// ----------------------- fused flash attention ------------------------------
// ctx[b, q, h*64+d] = softmax(Q K^T) V   (scale pre-folded into Q weights)
// Q/K/V are column slices of the packed QKV tensor (leading dim ld).
__global__ __launch_bounds__(256)
void flash_attn(const __half* __restrict__ QKV, int ld, __half* __restrict__ ctx)
{
    extern __shared__ char sm[];
    char* Qs = sm;                       // 16 KB
    char* Kb[2] = { sm + 16384, sm + 32768 };
    char* Vb[2] = { sm + 24576, sm + 40960 };

    const int tid = threadIdx.x, wid = tid >> 5, lane = tid & 31;
    const int gid = lane >> 2, tig = lane & 3;
    const int qt = blockIdx.x, bh = blockIdx.y;
    const int b = bh >> 4, hh = bh & 15;

    const __half* Qg = QKV + ((size_t)(b * 1024 + qt * 128) * ld + hh * 64);
    const __half* Kg = QKV + ((size_t)b * 1024 * ld + 1024 + hh * 64);
    const __half* Vg = QKV + ((size_t)b * 1024 * ld + 2048 + hh * 64);

    // stage Q (128 x 64 half = 128B/row, SW128) via cp.async
    #pragma unroll
    for (int i = 0; i < 4; i++) {
        int id = tid + i * 256;
        int r = id >> 3, cc = id & 7;
        cp16(smem_addr(Qs + sw128(r * 128 + cc * 16)), Qg + (size_t)r * ld + cc * 8);
    }
    cp_commit();

    auto stage_kv = [&](int kt, int buf) {
        #pragma unroll
        for (int i = 0; i < 2; i++) {
            int id = tid + i * 256;
            int r = id >> 3, cc = id & 7;
            int swb = sw128(r * 128 + cc * 16);
            cp16(smem_addr(Kb[buf] + swb), Kg + (size_t)(kt * 64 + r) * ld + cc * 8);
            cp16(smem_addr(Vb[buf] + swb), Vg + (size_t)(kt * 64 + r) * ld + cc * 8);
        }
    };
    stage_kv(0, 0);
    cp_commit();

    cp_wait<1>();          // Q group done
    __syncthreads();

    uint32_t qf[4][4];
    #pragma unroll
    for (int ks = 0; ks < 4; ks++) {
        int row = wid * 16 + (lane & 15);
        int colb = ks * 32 + ((lane & 16) ? 16 : 0);
        ldmx4(qf[ks], smem_addr(Qs + sw128(row * 128 + colb)));
    }

    float m0 = -1e30f, m1 = -1e30f, l0 = 0.f, l1 = 0.f;
    float o[8][4];
    #pragma unroll
    for (int nt = 0; nt < 8; nt++)
        #pragma unroll
        for (int e = 0; e < 4; e++) o[nt][e] = 0.f;

    for (int kt = 0; kt < 16; kt++) {
        const int buf = kt & 1;
        if (kt + 1 < 16) { stage_kv(kt + 1, buf ^ 1); cp_commit(); cp_wait<1>(); }
        else             { cp_wait<0>(); }
        __syncthreads();

        // ---- S = Q @ K^T ----
        float s[8][4];
        #pragma unroll
        for (int nt = 0; nt < 8; nt++)
            #pragma unroll
            for (int e = 0; e < 4; e++) s[nt][e] = 0.f;

        #pragma unroll
        for (int ks = 0; ks < 4; ks++) {
            uint32_t kb[8][2];
            #pragma unroll
            for (int ntp = 0; ntp < 4; ntp++) {
                int row = ntp * 16 + (lane & 7) + ((lane & 16) ? 8 : 0);
                int colb = ks * 32 + ((lane & 8) ? 16 : 0);
                uint32_t t[4];
                ldmx4(t, smem_addr(Kb[buf] + sw128(row * 128 + colb)));
                kb[2*ntp][0] = t[0]; kb[2*ntp][1] = t[1];
                kb[2*ntp+1][0] = t[2]; kb[2*ntp+1][1] = t[3];
            }
            #pragma unroll
            for (int nt = 0; nt < 8; nt++)
                mma_f16(s[nt], qf[ks], kb[nt]);
        }

        // ---- online softmax ----
        float mc0 = -1e30f, mc1 = -1e30f;
        #pragma unroll
        for (int nt = 0; nt < 8; nt++) {
            mc0 = fmaxf(mc0, fmaxf(s[nt][0], s[nt][1]));
            mc1 = fmaxf(mc1, fmaxf(s[nt][2], s[nt][3]));
        }
        mc0 = fmaxf(mc0, __shfl_xor_sync(0xffffffffu, mc0, 1));
        mc0 = fmaxf(mc0, __shfl_xor_sync(0xffffffffu, mc0, 2));
        mc1 = fmaxf(mc1, __shfl_xor_sync(0xffffffffu, mc1, 1));
        mc1 = fmaxf(mc1, __shfl_xor_sync(0xffffffffu, mc1, 2));
        float mn0 = fmaxf(m0, mc0), mn1 = fmaxf(m1, mc1);
        float sc0 = __expf(m0 - mn0), sc1 = __expf(m1 - mn1);
        m0 = mn0; m1 = mn1;

        float rs0 = 0.f, rs1 = 0.f;
        uint32_t pf[8][2];
        #pragma unroll
        for (int nt = 0; nt < 8; nt++) {
            float p0 = __expf(s[nt][0] - mn0);
            float p1 = __expf(s[nt][1] - mn0);
            float p2 = __expf(s[nt][2] - mn1);
            float p3 = __expf(s[nt][3] - mn1);
            rs0 += p0 + p1; rs1 += p2 + p3;
            pf[nt][0] = pack_h2(p0, p1);
            pf[nt][1] = pack_h2(p2, p3);
        }
        rs0 += __shfl_xor_sync(0xffffffffu, rs0, 1);
        rs0 += __shfl_xor_sync(0xffffffffu, rs0, 2);
        rs1 += __shfl_xor_sync(0xffffffffu, rs1, 1);
        rs1 += __shfl_xor_sync(0xffffffffu, rs1, 2);
        l0 = l0 * sc0 + rs0;
        l1 = l1 * sc1 + rs1;
        #pragma unroll
        for (int nt = 0; nt < 8; nt++) {
            o[nt][0] *= sc0; o[nt][1] *= sc0;
            o[nt][2] *= sc1; o[nt][3] *= sc1;
        }

        // ---- O += P @ V ----
        #pragma unroll
        for (int ks = 0; ks < 4; ks++) {
            uint32_t vb[8][2];
            #pragma unroll
            for (int ntp = 0; ntp < 4; ntp++) {
                int row = ks * 16 + (lane & 7) + ((lane & 8) ? 8 : 0);
                int colb = ntp * 32 + ((lane & 16) ? 16 : 0);
                uint32_t t[4];
                asm volatile("ldmatrix.sync.aligned.m8n8.x4.trans.shared.b16 {%0,%1,%2,%3}, [%4];"
                    : "=r"(t[0]), "=r"(t[1]), "=r"(t[2]), "=r"(t[3])
                    : "r"(smem_addr(Vb[buf] + sw128(row * 128 + colb))));
                vb[2*ntp][0] = t[0]; vb[2*ntp][1] = t[1];
                vb[2*ntp+1][0] = t[2]; vb[2*ntp+1][1] = t[3];
            }
            uint32_t a[4] = { pf[2*ks][0], pf[2*ks][1], pf[2*ks+1][0], pf[2*ks+1][1] };
            #pragma unroll
            for (int nt = 0; nt < 8; nt++)
                mma_f16(o[nt], a, vb[nt]);
        }
        __syncthreads();
    }

    // ---- epilogue ----
    float inv0 = 1.f / l0, inv1 = 1.f / l1;
    const int row0 = b * 1024 + qt * 128 + wid * 16 + gid;
    #pragma unroll
    for (int nt = 0; nt < 8; nt++) {
        int col = hh * 64 + nt * 8 + 2 * tig;
        *(__half2*)(ctx + (size_t)row0 * 1024 + col) =
            __floats2half2_rn(o[nt][0] * inv0, o[nt][1] * inv0);
        *(__half2*)(ctx + (size_t)(row0 + 8) * 1024 + col) =
            __floats2half2_rn(o[nt][2] * inv1, o[nt][3] * inv1);
    }
}

// ------------- weight transpose (fp32 -> fp16, optional scale) --------------
__global__ __launch_bounds__(256)
void transpose_h_kernel(const float* __restrict__ in, int ldi,
                        __half* __restrict__ out, int ldo, float scale)
{
    __shared__ float t[32][33];
    const int r0 = blockIdx.y * 32, c0 = blockIdx.x * 32;
    const int tx = threadIdx.x & 31, ty = threadIdx.x >> 5;
    #pragma unroll
    for (int i = 0; i < 32; i += 8)
        t[ty + i][tx] = in[(long long)(r0 + ty + i) * ldi + c0 + tx];
    __syncthreads();
    #pragma unroll
    for (int i = 0; i < 32; i += 8)
        out[(long long)(c0 + ty + i) * ldo + r0 + tx] = __float2half(t[tx][ty + i] * scale);
}

// --------------------------- fp32 -> fp16 copy ------------------------------
__global__ __launch_bounds__(256)
void f2h_kernel(const float* __restrict__ in, __half* __restrict__ out)
{
    const long long i = ((long long)blockIdx.x * 256 + threadIdx.x) * 4;
    float4 v = *(const float4*)(in + i);
    __half2 a = __floats2half2_rn(v.x, v.y);
    __half2 b = __floats2half2_rn(v.z, v.w);
    *(uint2*)(out + i) = make_uint2(*(uint32_t*)&a, *(uint32_t*)&b);
}

// ---------------------- packed QKV bias construction ------------------------
__global__ __launch_bounds__(256)
void bias3_kernel(const float* __restrict__ bq, const float* __restrict__ bk,
                  const float* __restrict__ bv, float* __restrict__ b3)
{
    int i = blockIdx.x * 256 + threadIdx.x;
    float v;
    if (i < 1024)        v = bq[i] * 0.125f;
    else if (i < 2048)   v = bk[i - 1024];
    else                 v = bv[i - 2048];
    b3[i] = v;
}

// -------------------------- block reduce (256 thr) --------------------------
__device__ __forceinline__ float blk_sum256(float v)
{
    __shared__ float sm[8];
    const int lane = threadIdx.x & 31, w = threadIdx.x >> 5;
    #pragma unroll
    for (int o = 16; o; o >>= 1) v += __shfl_xor_sync(0xffffffffu, v, o);
    if (lane == 0) sm[w] = v;
    __syncthreads();
    if (w == 0) {
        float r = (lane < 8) ? sm[lane] : 0.f;
        #pragma unroll
        for (int o = 4; o; o >>= 1) r += __shfl_xor_sync(0xffffffffu, r, o);
        if (lane == 0) sm[0] = r;
    }
    __syncthreads();
    float r = sm[0];
    __syncthreads();
    return r;
}

// ------------------------------- adaLN --------------------------------------
// writes fp32 out and fp16 outh
__global__ __launch_bounds__(256)
void ada_ln_kernel(const float* __restrict__ in, const float* __restrict__ vol,
                   const float* __restrict__ w, const float* __restrict__ b,
                   const float* __restrict__ gamma, const float* __restrict__ beta,
                   const float* __restrict__ vsw, const float* __restrict__ vsb,
                   float* __restrict__ out, __half* __restrict__ outh)
{
    const long long row = blockIdx.x;
    const int t = threadIdx.x;
    float4 v = *(const float4*)(in + row * 1024 + t * 4);

    float mu = blk_sum256(v.x + v.y + v.z + v.w) * (1.f / 1024.f);
    float dx = v.x - mu, dy = v.y - mu, dz = v.z - mu, dw = v.w - mu;
    float var = blk_sum256(dx * dx + dy * dy + dz * dz + dw * dw) * (1.f / 1024.f);
    float inv = rsqrtf(var + 1e-5f);

    float vs = 1.f / (1.f + expf(-(vol[row] * (*vsw) + (*vsb))));
    float k1 = (1.f + vs) * (*gamma);
    float k0 = *beta;

    float4 w4 = *(const float4*)(w + t * 4);
    float4 b4 = *(const float4*)(b + t * 4);
    float4 o;
    o.x = (dx * inv * w4.x + b4.x) * k1 + k0;
    o.y = (dy * inv * w4.y + b4.y) * k1 + k0;
    o.z = (dz * inv * w4.z + b4.z) * k1 + k0;
    o.w = (dw * inv * w4.w + b4.w) * k1 + k0;
    *(float4*)(out + row * 1024 + t * 4) = o;
    __half2 ha = __floats2half2_rn(o.x, o.y);
    __half2 hb = __floats2half2_rn(o.z, o.w);
    *(uint2*)(outh + row * 1024 + t * 4) = make_uint2(*(uint32_t*)&ha, *(uint32_t*)&hb);
}

// -------- combine (x1*(2-g) + ffn*g) then adaLN2 -> out ----------------------
__global__ __launch_bounds__(256)
void combine_ada_ln_kernel(const float* __restrict__ x1, const float* __restrict__ f,
                           const float* __restrict__ g,  const float* __restrict__ vol,
                           const float* __restrict__ w,  const float* __restrict__ b,
                           const float* __restrict__ gamma, const float* __restrict__ beta,
                           const float* __restrict__ vsw, const float* __restrict__ vsb,
                           float* __restrict__ out)
{
    const long long row = blockIdx.x;
    const int t = threadIdx.x;
    float4 a  = *(const float4*)(x1 + row * 1024 + t * 4);
    float4 ff = *(const float4*)(f  + row * 1024 + t * 4);
    float4 gg = *(const float4*)(g  + row * 1024 + t * 4);

    float4 v;
    v.x = a.x * (2.f - gg.x) + ff.x * gg.x;
    v.y = a.y * (2.f - gg.y) + ff.y * gg.y;
    v.z = a.z * (2.f - gg.z) + ff.z * gg.z;
    v.w = a.w * (2.f - gg.w) + ff.w * gg.w;

    float mu = blk_sum256(v.x + v.y + v.z + v.w) * (1.f / 1024.f);
    float dx = v.x - mu, dy = v.y - mu, dz = v.z - mu, dw = v.w - mu;
    float var = blk_sum256(dx * dx + dy * dy + dz * dz + dw * dw) * (1.f / 1024.f);
    float inv = rsqrtf(var + 1e-5f);

    float vs = 1.f / (1.f + expf(-(vol[row] * (*vsw) + (*vsb))));
    float k1 = (1.f + vs) * (*gamma);
    float k0 = *beta;

    float4 w4 = *(const float4*)(w + t * 4);
    float4 b4 = *(const float4*)(b + t * 4);
    float4 o;
    o.x = (dx * inv * w4.x + b4.x) * k1 + k0;
    o.y = (dy * inv * w4.y + b4.y) * k1 + k0;
    o.z = (dz * inv * w4.z + b4.z) * k1 + k0;
    o.w = (dw * inv * w4.w + b4.w) * k1 + k0;
    *(float4*)(out + row * 1024 + t * 4) = o;
}

// ------------------------------ launcher ------------------------------------
#define SMEM_GEMM  65536
#define SMEM_FLASH 49152

extern "C" void kernel_launch(void* const* d_in, const int* in_sizes, int n_in,
                              void* d_out, int out_size)
{
    const float* x      = (const float*)d_in[0];
    const float* vol    = (const float*)d_in[1];
    const float* Wq     = (const float*)d_in[2];
    const float* bq     = (const float*)d_in[3];
    const float* Wk     = (const float*)d_in[4];
    const float* bk     = (const float*)d_in[5];
    const float* Wv     = (const float*)d_in[6];
    const float* bv     = (const float*)d_in[7];
    const float* Wo     = (const float*)d_in[8];
    const float* bo     = (const float*)d_in[9];
    const float* ln1w   = (const float*)d_in[10];
    const float* ln1b   = (const float*)d_in[11];
    const float* gamma1 = (const float*)d_in[12];
    const float* beta1  = (const float*)d_in[13];
    const float* vs1w   = (const float*)d_in[14];
    const float* vs1b   = (const float*)d_in[15];
    const float* fw1    = (const float*)d_in[16];
    const float* fb1    = (const float*)d_in[17];
    const float* fw2    = (const float*)d_in[18];
    const float* fb2    = (const float*)d_in[19];
    const float* gw1    = (const float*)d_in[20];
    const float* gb1    = (const float*)d_in[21];
    const float* gw2    = (const float*)d_in[22];
    const float* gb2    = (const float*)d_in[23];
    const float* ln2w   = (const float*)d_in[24];
    const float* ln2b   = (const float*)d_in[25];
    const float* gamma2 = (const float*)d_in[26];
    const float* beta2  = (const float*)d_in[27];
    const float* vs2w   = (const float*)d_in[28];
    const float* vs2b   = (const float*)d_in[29];
    float* out = (float*)d_out;

    __half *xh, *QKV, *ctx, *h, *g1, *x1h;
    float *xr, *x1, *f, *g, *bqkv;
    __half *WqkvT, *WoT, *fw1T, *fw2T, *gw1T, *gw2T;
    cudaGetSymbolAddress((void**)&xh,    g_xh);
    cudaGetSymbolAddress((void**)&QKV,   g_QKV);
    cudaGetSymbolAddress((void**)&ctx,   g_ctx);
    cudaGetSymbolAddress((void**)&xr,    g_xr);
    cudaGetSymbolAddress((void**)&x1,    g_x1);
    cudaGetSymbolAddress((void**)&x1h,   g_x1h);
    cudaGetSymbolAddress((void**)&h,     g_h);
    cudaGetSymbolAddress((void**)&f,     g_f);
    cudaGetSymbolAddress((void**)&g1,    g_g1);
    cudaGetSymbolAddress((void**)&g,     g_g);
    cudaGetSymbolAddress((void**)&WqkvT, g_WqkvT);
    cudaGetSymbolAddress((void**)&bqkv,  g_bqkv);
    cudaGetSymbolAddress((void**)&WoT,   g_WoT);
    cudaGetSymbolAddress((void**)&fw1T,  g_fw1T);
    cudaGetSymbolAddress((void**)&fw2T,  g_fw2T);
    cudaGetSymbolAddress((void**)&gw1T,  g_gw1T);
    cudaGetSymbolAddress((void**)&gw2T,  g_gw2T);

    cudaFuncSetAttribute((const void*)mma_gemm<__half>, cudaFuncAttributeMaxDynamicSharedMemorySize, SMEM_GEMM);
    cudaFuncSetAttribute((const void*)mma_gemm<float>,  cudaFuncAttributeMaxDynamicSharedMemorySize, SMEM_GEMM);
    cudaFuncSetAttribute((const void*)flash_attn,       cudaFuncAttributeMaxDynamicSharedMemorySize, SMEM_FLASH);

    // ---- weight transposes to fp16 (Wq scaled by 1/8 into packed QKV) ----
    transpose_h_kernel<<<dim3(Hsz/32, Hsz/32), 256>>>(Wq, Hsz, WqkvT,            Hsz, 0.125f);
    transpose_h_kernel<<<dim3(Hsz/32, Hsz/32), 256>>>(Wk, Hsz, WqkvT + (size_t)Hsz*Hsz,   Hsz, 1.f);
    transpose_h_kernel<<<dim3(Hsz/32, Hsz/32), 256>>>(Wv, Hsz, WqkvT + (size_t)2*Hsz*Hsz, Hsz, 1.f);
    bias3_kernel<<<H3/256, 256>>>(bq, bk, bv, bqkv);
    transpose_h_kernel<<<dim3(Hsz/32, Hsz/32), 256>>>(Wo, Hsz, WoT, Hsz, 1.f);
    transpose_h_kernel<<<dim3(HF/32,  Hsz/32), 256>>>(fw1, HF, fw1T, Hsz, 1.f);
    transpose_h_kernel<<<dim3(Hsz/32, HF/32 ), 256>>>(fw2, Hsz, fw2T, HF, 1.f);
    transpose_h_kernel<<<dim3(HG/32,  Hsz/32), 256>>>(gw1, HG, gw1T, Hsz, 1.f);
    transpose_h_kernel<<<dim3(Hsz/32, HG/32 ), 256>>>(gw2, Hsz, gw2T, HG, 1.f);
    f2h_kernel<<<(size_t)Mrows*Hsz/1024, 256>>>(x, xh);

    // ---- fused QKV projection (one GEMM, N=3072) ----
    mma_gemm<__half><<<dim3(24,64),256,SMEM_GEMM>>>(xh,Hsz, WqkvT,Hsz, QKV,H3, bqkv,nullptr, Hsz, 0);

    // ---- fused attention ----
    flash_attn<<<dim3(8, Bsz*NH), 256, SMEM_FLASH>>>(QKV, H3, ctx);

    // ---- O projection + residual ----
    mma_gemm<float><<<dim3(8,64),256,SMEM_GEMM>>>(ctx,Hsz, WoT,Hsz, xr,Hsz, bo,x, Hsz, 0);

    // ---- adaLN1 (fp32 + fp16 outputs) ----
    ada_ln_kernel<<<Mrows,256>>>(xr, vol, ln1w, ln1b, gamma1, beta1, vs1w, vs1b, x1, x1h);

    // ---- FFN ----
    mma_gemm<__half><<<dim3(32,64),256,SMEM_GEMM>>>(x1h,Hsz, fw1T,Hsz, h,HF,  fb1,nullptr, Hsz, 1);
    mma_gemm<float> <<<dim3(8,64), 256,SMEM_GEMM>>>(h,HF,   fw2T,HF,  f,Hsz, fb2,nullptr, HF,  0);

    // ---- gate ----
    mma_gemm<__half><<<dim3(4,64),256,SMEM_GEMM>>>(x1h,Hsz, gw1T,Hsz, g1,HG, gb1,nullptr, Hsz, 2);
    mma_gemm<float> <<<dim3(8,64),256,SMEM_GEMM>>>(g1,HG,   gw2T,HG,  g,Hsz, gb2,nullptr, HG,  3);

    // ---- combine + adaLN2 -> out ----
    combine_ada_ln_kernel<<<Mrows,256>>>(x1, f, g, vol, ln2w, ln2b, gamma2, beta2, vs2w, vs2b, out);
}